// round 12
// baseline (speedup 1.0000x reference)
#include <cuda_runtime.h>
#include <cuda_fp16.h>
#include <math.h>
#include <stdint.h>

#define T_TOK 4096
#define HIDD  2048
#define NH    16
#define HD    128
#define SEQ   2048
#define NB    2
#define NE    8
#define INTER 4096
#define CAP   4096
#define EPS   1e-5f
#define QKVW  6144

// ---------------- scratch ----------------
__device__ __half g_xn1h[(size_t)T_TOK * HIDD];
__device__ __half g_xn1l[(size_t)T_TOK * HIDD];
__device__ __half g_qkvh[(size_t)T_TOK * QKVW];
__device__ __half g_qkvl[(size_t)T_TOK * QKVW];
__device__ __half g_atth[(size_t)T_TOK * HIDD];
__device__ __half g_attl[(size_t)T_TOK * HIDD];
__device__ float  g_x2  [(size_t)T_TOK * HIDD];
__device__ float  g_xn2 [(size_t)T_TOK * HIDD];
__device__ __half g_xn2h[(size_t)T_TOK * HIDD];
__device__ __half g_acth[(size_t)NE * CAP * INTER];
__device__ float  g_yb  [(size_t)NE * CAP * HIDD];
__device__ __half g_wqkvh[(size_t)QKVW * HIDD];
__device__ __half g_wqkvl[(size_t)QKVW * HIDD];
__device__ __half g_woh[(size_t)HIDD * HIDD];
__device__ __half g_wol[(size_t)HIDD * HIDD];
__device__ __half g_wguh[(size_t)NE * 2 * INTER * HIDD];  // interleaved gate/up rows
__device__ __half g_wdh[(size_t)NE * HIDD * INTER];
__device__ int    g_cnt[NE];
__device__ int    g_gather[NE * CAP];
__device__ int2   g_slots[T_TOK];
__device__ float2 g_wts[T_TOK];

// ---------------- helpers ----------------
__device__ __forceinline__ void mma16(float* c, const uint32_t* a, uint32_t b0, uint32_t b1) {
    asm volatile(
        "mma.sync.aligned.m16n8k16.row.col.f32.f16.f16.f32 "
        "{%0,%1,%2,%3}, {%4,%5,%6,%7}, {%8,%9}, {%0,%1,%2,%3};"
        : "+f"(c[0]), "+f"(c[1]), "+f"(c[2]), "+f"(c[3])
        : "r"(a[0]), "r"(a[1]), "r"(a[2]), "r"(a[3]), "r"(b0), "r"(b1));
}
__device__ __forceinline__ void ldm_x4(uint32_t* r, uint32_t saddr) {
    asm volatile("ldmatrix.sync.aligned.m8n8.x4.shared.b16 {%0,%1,%2,%3}, [%4];"
                 : "=r"(r[0]), "=r"(r[1]), "=r"(r[2]), "=r"(r[3]) : "r"(saddr));
}
__device__ __forceinline__ void cp_async16(void* smem, const void* gmem) {
    uint32_t s = (uint32_t)__cvta_generic_to_shared(smem);
    asm volatile("cp.async.cg.shared.global [%0], [%1], 16;\n" :: "r"(s), "l"(gmem));
}
__device__ __forceinline__ void cp_commit() { asm volatile("cp.async.commit_group;\n"); }
template <int N>
__device__ __forceinline__ void cp_wait() { asm volatile("cp.async.wait_group %0;\n" :: "n"(N)); }
__device__ __forceinline__ uint32_t ld32s(const __half* p) { return *(const uint32_t*)p; }
__device__ __forceinline__ void split16(float x, __half& h, __half& l) {
    h = __float2half_rn(x);
    l = __float2half_rn(x - __half2float(h));
}

// =========================================================================
// unified fp16 GEMM: C[M,N] = A[M,K] @ B[N,K]^T
//   NSTAGE-deep cp.async ring (wait_group NSTAGE-2, one commit per iter)
// =========================================================================
#define HBM 128
#define HBN 128
#define HBK 32
#define HS  40
#define HTILE (128 * HS)

template <int NSTAGE, bool SPLIT, bool MOE, bool GATHER, bool EPI16, bool SWIGLU>
__global__ __launch_bounds__(256)
void hgemm(const __half* __restrict__ Ah, const __half* __restrict__ Al,
           const __half* __restrict__ Bh, const __half* __restrict__ Bl,
           const float* __restrict__ resid, float* __restrict__ Cf,
           __half* __restrict__ Ch, __half* __restrict__ Cl,
           int M, int N, int K, size_t aes, size_t bes, size_t ces) {
    extern __shared__ __half hsm[];
    __shared__ int rows_s[HBM];
    const int t = threadIdx.x, lane = t & 31, wid = t >> 5;
    const int lq = lane >> 2, lr = lane & 3;
    const int lrow16 = lane & 15, lsel = lane >> 4;
    const int rb = (wid >> 2) * 64, cb = (wid & 3) * 32;
    const int bm = blockIdx.y * HBM, bn = blockIdx.x * HBN;

    if (MOE) {
        int e = blockIdx.z;
        M = g_cnt[e];
        if (bm >= M) return;
        Ah += (size_t)e * aes;
        Bh += (size_t)e * bes;
        if (SWIGLU) Ch += (size_t)e * ces; else Cf += (size_t)e * ces;
        if (GATHER && t < HBM) {
            int r = bm + t;
            if (r >= M) r = M - 1;
            rows_s[t] = g_gather[e * CAP + r];
        }
        if (GATHER) __syncthreads();
    }

    const uint32_t sbase = (uint32_t)__cvta_generic_to_shared(hsm);
    const int IA_H = 0, IA_L = 1, IB_H = SPLIT ? 2 : 1, IB_L = 3;
    auto tgen = [&](int arr, int buf) { return hsm + (size_t)(arr * NSTAGE + buf) * HTILE; };
    auto tsh  = [&](int arr, int buf) { return sbase + (uint32_t)(arr * NSTAGE + buf) * HTILE * 2; };

    float acc[4][4][4];
#pragma unroll
    for (int i = 0; i < 4; i++)
#pragma unroll
        for (int j = 0; j < 4; j++)
#pragma unroll
            for (int f = 0; f < 4; f++) acc[i][j][f] = 0.f;

    int lrow[2], lsg[2];
    size_t aoff[2], boff[2];
#pragma unroll
    for (int i = 0; i < 2; i++) {
        int slot = t + 256 * i;
        lrow[i] = slot >> 2; lsg[i] = (slot & 3) * 8;
        size_t ar = GATHER ? (size_t)rows_s[lrow[i]] : (size_t)(bm + lrow[i]);
        aoff[i] = ar * K + lsg[i];
        boff[i] = (size_t)(bn + lrow[i]) * K + lsg[i];
    }

    auto issue = [&](int c, int buf) {
        const int k0 = c * HBK;
#pragma unroll
        for (int i = 0; i < 2; i++) {
            cp_async16(tgen(IA_H, buf) + lrow[i] * HS + lsg[i], Ah + aoff[i] + k0);
            cp_async16(tgen(IB_H, buf) + lrow[i] * HS + lsg[i], Bh + boff[i] + k0);
            if (SPLIT) {
                cp_async16(tgen(IA_L, buf) + lrow[i] * HS + lsg[i], Al + aoff[i] + k0);
                cp_async16(tgen(IB_L, buf) + lrow[i] * HS + lsg[i], Bl + boff[i] + k0);
            }
        }
    };

    auto compute = [&](int buf) {
        const uint32_t tAh = tsh(IA_H, buf), tBh = tsh(IB_H, buf);
        const uint32_t tAl = tsh(IA_L, buf), tBl = tsh(IB_L, buf);
#pragma unroll
        for (int ks = 0; ks < 2; ks++) {
            const int k0 = ks * 16;
            uint32_t ah[4][4], al[4][4], bh[4][2], bl[4][2];
#pragma unroll
            for (int mt = 0; mt < 4; mt++) {
                uint32_t off = (uint32_t)(((rb + mt * 16 + lrow16) * HS + k0 + lsel * 8) * 2);
                ldm_x4(ah[mt], tAh + off);
                if (SPLIT) ldm_x4(al[mt], tAl + off);
            }
#pragma unroll
            for (int np = 0; np < 2; np++) {
                uint32_t off = (uint32_t)(((cb + np * 16 + lrow16) * HS + k0 + lsel * 8) * 2);
                uint32_t r[4];
                ldm_x4(r, tBh + off);
                bh[2 * np][0] = r[0]; bh[2 * np][1] = r[2];
                bh[2 * np + 1][0] = r[1]; bh[2 * np + 1][1] = r[3];
                if (SPLIT) {
                    ldm_x4(r, tBl + off);
                    bl[2 * np][0] = r[0]; bl[2 * np][1] = r[2];
                    bl[2 * np + 1][0] = r[1]; bl[2 * np + 1][1] = r[3];
                }
            }
#pragma unroll
            for (int mt = 0; mt < 4; mt++)
#pragma unroll
                for (int nt = 0; nt < 4; nt++) {
                    mma16(acc[mt][nt], ah[mt], bh[nt][0], bh[nt][1]);
                    if (SPLIT) {
                        mma16(acc[mt][nt], ah[mt], bl[nt][0], bl[nt][1]);
                        mma16(acc[mt][nt], al[mt], bh[nt][0], bh[nt][1]);
                    }
                }
        }
    };

    const int nk = K / HBK;
    // prologue: fill NSTAGE-1 stages, one commit each
#pragma unroll
    for (int c = 0; c < NSTAGE - 1; c++) {
        if (c < nk) issue(c, c);
        cp_commit();
    }
    for (int c = 0; c < nk; c++) {
        cp_wait<NSTAGE - 2>();        // chunk c resident (in-order groups)
        __syncthreads();
        compute(c % NSTAGE);
        const int n = c + NSTAGE - 1;
        if (n < nk) issue(n, n % NSTAGE);
        cp_commit();                   // uniform: one group per iteration
    }

#pragma unroll
    for (int mt = 0; mt < 4; mt++)
#pragma unroll
        for (int nt = 0; nt < 4; nt++) {
            int r0g = bm + rb + mt * 16 + lq;
            int r1g = r0g + 8;
            int c0 = bn + cb + nt * 8 + lr * 2;
            if (SWIGLU) {
                int oc = c0 >> 1;
                if (r0g < M) {
                    float g = acc[mt][nt][0], u = acc[mt][nt][1];
                    Ch[(size_t)r0g * INTER + oc] =
                        __float2half_rn(g / (1.f + __expf(-g)) * u);
                }
                if (r1g < M) {
                    float g = acc[mt][nt][2], u = acc[mt][nt][3];
                    Ch[(size_t)r1g * INTER + oc] =
                        __float2half_rn(g / (1.f + __expf(-g)) * u);
                }
            } else if (EPI16) {
                __half h0, l0, h1, l1;
                split16(acc[mt][nt][0], h0, l0); split16(acc[mt][nt][1], h1, l1);
                *(__half2*)(Ch + (size_t)r0g * N + c0) = __halves2half2(h0, h1);
                *(__half2*)(Cl + (size_t)r0g * N + c0) = __halves2half2(l0, l1);
                split16(acc[mt][nt][2], h0, l0); split16(acc[mt][nt][3], h1, l1);
                *(__half2*)(Ch + (size_t)r1g * N + c0) = __halves2half2(h0, h1);
                *(__half2*)(Cl + (size_t)r1g * N + c0) = __halves2half2(l0, l1);
            } else {
                if (!MOE || r0g < M) {
                    float2 v0 = make_float2(acc[mt][nt][0], acc[mt][nt][1]);
                    if (resid) {
                        v0.x += resid[(size_t)r0g * N + c0];
                        v0.y += resid[(size_t)r0g * N + c0 + 1];
                    }
                    *(float2*)(Cf + (size_t)r0g * N + c0) = v0;
                }
                if (!MOE || r1g < M) {
                    float2 v1 = make_float2(acc[mt][nt][2], acc[mt][nt][3]);
                    if (resid) {
                        v1.x += resid[(size_t)r1g * N + c0];
                        v1.y += resid[(size_t)r1g * N + c0 + 1];
                    }
                    *(float2*)(Cf + (size_t)r1g * N + c0) = v1;
                }
            }
        }
}

// =========================================================================
// flash attention: fp16-split mma, causal, 64q x 64k tiles, 4 warps
// =========================================================================
#define QS 136
#define VS 72
#define FLASH_SMEM ((4 * 64 * QS + 2 * 128 * VS) * 2)

__global__ __launch_bounds__(128)
void flash_mma_k() {
    extern __shared__ __half fsm[];
    __half* Qh  = fsm;
    __half* Ql  = Qh + 64 * QS;
    __half* Kh  = Ql + 64 * QS;
    __half* Kl  = Kh + 64 * QS;
    __half* Vth = Kl + 64 * QS;
    __half* Vtl = Vth + 128 * VS;

    const int qt = blockIdx.x, head = blockIdx.y, b = blockIdx.z;
    const int t = threadIdx.x, wid = t >> 5, lane = t & 31;
    const int lq = lane >> 2, lr = lane & 3;
    const int wr = wid * 16;
    const float scale = 0.08838834764831845f;
    const size_t base = (size_t)b * SEQ * QKVW;
    const size_t qoff = (size_t)head * HD;
    const size_t koff = 2048 + qoff, voff = 4096 + qoff;

    for (int i = t; i < 64 * 16; i += 128) {
        int r = i >> 4, sg = (i & 15) * 8;
        size_t g = base + (size_t)(qt * 64 + r) * QKVW + qoff + sg;
        *(uint4*)(Qh + r * QS + sg) = *(const uint4*)(g_qkvh + g);
        *(uint4*)(Ql + r * QS + sg) = *(const uint4*)(g_qkvl + g);
    }

    float out[16][4];
#pragma unroll
    for (int i = 0; i < 16; i++)
#pragma unroll
        for (int j = 0; j < 4; j++) out[i][j] = 0.f;
    float m0 = -INFINITY, m1 = -INFINITY, l0 = 0.f, l1 = 0.f;

    for (int kt = 0; kt <= qt; kt++) {
        __syncthreads();
        for (int i = t; i < 64 * 16; i += 128) {
            int r = i >> 4, sg = (i & 15) * 8;
            size_t g = base + (size_t)(kt * 64 + r) * QKVW + koff + sg;
            *(uint4*)(Kh + r * QS + sg) = *(const uint4*)(g_qkvh + g);
            *(uint4*)(Kl + r * QS + sg) = *(const uint4*)(g_qkvl + g);
        }
        for (int i = t; i < 64 * 64; i += 128) {
            int r = i >> 6, dp = i & 63;
            size_t g = base + (size_t)(kt * 64 + r) * QKVW + voff + dp * 2;
            __half2 vh = *(const __half2*)(g_qkvh + g);
            __half2 vl = *(const __half2*)(g_qkvl + g);
            Vth[(2 * dp) * VS + r]     = __low2half(vh);
            Vth[(2 * dp + 1) * VS + r] = __high2half(vh);
            Vtl[(2 * dp) * VS + r]     = __low2half(vl);
            Vtl[(2 * dp + 1) * VS + r] = __high2half(vl);
        }
        __syncthreads();

        float s[8][4];
#pragma unroll
        for (int i = 0; i < 8; i++)
#pragma unroll
            for (int j = 0; j < 4; j++) s[i][j] = 0.f;

        for (int kc = 0; kc < 8; kc++) {
            uint32_t ah[4], al[4];
            const __half* qp = Qh + (wr + lq) * QS + kc * 16 + lr * 2;
            const __half* ql = Ql + (wr + lq) * QS + kc * 16 + lr * 2;
            ah[0] = ld32s(qp);     ah[1] = ld32s(qp + 8 * QS);
            ah[2] = ld32s(qp + 8); ah[3] = ld32s(qp + 8 * QS + 8);
            al[0] = ld32s(ql);     al[1] = ld32s(ql + 8 * QS);
            al[2] = ld32s(ql + 8); al[3] = ld32s(ql + 8 * QS + 8);
#pragma unroll
            for (int nt = 0; nt < 8; nt++) {
                const __half* kp = Kh + (nt * 8 + lq) * QS + kc * 16 + lr * 2;
                const __half* kl = Kl + (nt * 8 + lq) * QS + kc * 16 + lr * 2;
                uint32_t bh0 = ld32s(kp), bh1 = ld32s(kp + 8);
                uint32_t bl0 = ld32s(kl), bl1 = ld32s(kl + 8);
                mma16(s[nt], ah, bh0, bh1);
                mma16(s[nt], ah, bl0, bl1);
                mma16(s[nt], al, bh0, bh1);
            }
        }

        const bool diag = (kt == qt);
#pragma unroll
        for (int nt = 0; nt < 8; nt++)
#pragma unroll
            for (int cc = 0; cc < 4; cc++) {
                float v = s[nt][cc] * scale;
                if (diag) {
                    int col = nt * 8 + lr * 2 + (cc & 1);
                    int row = wr + lq + ((cc >= 2) ? 8 : 0);
                    if (col > row) v = -INFINITY;
                }
                s[nt][cc] = v;
            }

        float mx0 = m0, mx1 = m1;
#pragma unroll
        for (int nt = 0; nt < 8; nt++) {
            mx0 = fmaxf(mx0, fmaxf(s[nt][0], s[nt][1]));
            mx1 = fmaxf(mx1, fmaxf(s[nt][2], s[nt][3]));
        }
        mx0 = fmaxf(mx0, __shfl_xor_sync(0xffffffffu, mx0, 1));
        mx0 = fmaxf(mx0, __shfl_xor_sync(0xffffffffu, mx0, 2));
        mx1 = fmaxf(mx1, __shfl_xor_sync(0xffffffffu, mx1, 1));
        mx1 = fmaxf(mx1, __shfl_xor_sync(0xffffffffu, mx1, 2));
        float a0 = __expf(m0 - mx0), a1 = __expf(m1 - mx1);
        m0 = mx0; m1 = mx1;
        float sum0 = 0.f, sum1 = 0.f;
#pragma unroll
        for (int nt = 0; nt < 8; nt++) {
            s[nt][0] = __expf(s[nt][0] - mx0);
            s[nt][1] = __expf(s[nt][1] - mx0);
            s[nt][2] = __expf(s[nt][2] - mx1);
            s[nt][3] = __expf(s[nt][3] - mx1);
            sum0 += s[nt][0] + s[nt][1];
            sum1 += s[nt][2] + s[nt][3];
        }
        sum0 += __shfl_xor_sync(0xffffffffu, sum0, 1);
        sum0 += __shfl_xor_sync(0xffffffffu, sum0, 2);
        sum1 += __shfl_xor_sync(0xffffffffu, sum1, 1);
        sum1 += __shfl_xor_sync(0xffffffffu, sum1, 2);
        l0 = l0 * a0 + sum0;
        l1 = l1 * a1 + sum1;

#pragma unroll
        for (int nt = 0; nt < 16; nt++) {
            out[nt][0] *= a0; out[nt][1] *= a0;
            out[nt][2] *= a1; out[nt][3] *= a1;
        }

#pragma unroll
        for (int kc = 0; kc < 4; kc++) {
            const int t0 = 2 * kc, t1 = 2 * kc + 1;
            uint32_t ph[4], pl[4];
            {
                __half2 h, l;
                h = __floats2half2_rn(s[t0][0], s[t0][1]);
                l = __floats2half2_rn(s[t0][0] - __low2float(h), s[t0][1] - __high2float(h));
                ph[0] = *(uint32_t*)&h; pl[0] = *(uint32_t*)&l;
                h = __floats2half2_rn(s[t0][2], s[t0][3]);
                l = __floats2half2_rn(s[t0][2] - __low2float(h), s[t0][3] - __high2float(h));
                ph[1] = *(uint32_t*)&h; pl[1] = *(uint32_t*)&l;
                h = __floats2half2_rn(s[t1][0], s[t1][1]);
                l = __floats2half2_rn(s[t1][0] - __low2float(h), s[t1][1] - __high2float(h));
                ph[2] = *(uint32_t*)&h; pl[2] = *(uint32_t*)&l;
                h = __floats2half2_rn(s[t1][2], s[t1][3]);
                l = __floats2half2_rn(s[t1][2] - __low2float(h), s[t1][3] - __high2float(h));
                ph[3] = *(uint32_t*)&h; pl[3] = *(uint32_t*)&l;
            }
#pragma unroll
            for (int nt = 0; nt < 16; nt++) {
                const __half* vp = Vth + (nt * 8 + lq) * VS + kc * 16 + lr * 2;
                const __half* vl = Vtl + (nt * 8 + lq) * VS + kc * 16 + lr * 2;
                uint32_t bh0 = ld32s(vp), bh1 = ld32s(vp + 8);
                uint32_t bl0 = ld32s(vl), bl1 = ld32s(vl + 8);
                mma16(out[nt], ph, bh0, bh1);
                mma16(out[nt], ph, bl0, bl1);
                mma16(out[nt], pl, bh0, bh1);
            }
        }
    }

    const float inv0 = 1.f / l0, inv1 = 1.f / l1;
    const int row0 = qt * 64 + wr + lq;
    const size_t o0 = ((size_t)b * SEQ + row0) * HIDD + head * HD;
    const size_t o1 = o0 + 8 * HIDD;
#pragma unroll
    for (int nt = 0; nt < 16; nt++) {
        int c = nt * 8 + lr * 2;
        __half h0, lo0, h1, lo1;
        split16(out[nt][0] * inv0, h0, lo0);
        split16(out[nt][1] * inv0, h1, lo1);
        *(__half2*)(g_atth + o0 + c) = __halves2half2(h0, h1);
        *(__half2*)(g_attl + o0 + c) = __halves2half2(lo0, lo1);
        split16(out[nt][2] * inv1, h0, lo0);
        split16(out[nt][3] * inv1, h1, lo1);
        *(__half2*)(g_atth + o1 + c) = __halves2half2(h0, h1);
        *(__half2*)(g_attl + o1 + c) = __halves2half2(lo0, lo1);
    }
}

// ---------------- RMSNorm ----------------
__global__ void rmsnorm_k(const float* __restrict__ x, const float* __restrict__ w,
                          float* __restrict__ yf, __half* __restrict__ yh,
                          __half* __restrict__ yl) {
    int tok = blockIdx.x;
    const float* xr = x + (size_t)tok * HIDD;
    float s = 0.f;
    for (int i = threadIdx.x * 4; i < HIDD; i += blockDim.x * 4) {
        float4 v = *(const float4*)(xr + i);
        s += v.x * v.x + v.y * v.y + v.z * v.z + v.w * v.w;
    }
    __shared__ float red[32];
    for (int o = 16; o > 0; o >>= 1) s += __shfl_xor_sync(0xffffffffu, s, o);
    if ((threadIdx.x & 31) == 0) red[threadIdx.x >> 5] = s;
    __syncthreads();
    if (threadIdx.x < 32) {
        float v = (threadIdx.x < (blockDim.x >> 5)) ? red[threadIdx.x] : 0.f;
        for (int o = 4; o > 0; o >>= 1) v += __shfl_xor_sync(0xffffffffu, v, o);
        if (threadIdx.x == 0) red[0] = rsqrtf(v / (float)HIDD + EPS);
    }
    __syncthreads();
    float sc = red[0];
    for (int i = threadIdx.x * 4; i < HIDD; i += blockDim.x * 4) {
        float4 v = *(const float4*)(xr + i);
        float4 wv = *(const float4*)(w + i);
        float4 o;
        o.x = v.x * sc * wv.x; o.y = v.y * sc * wv.y;
        o.z = v.z * sc * wv.z; o.w = v.w * sc * wv.w;
        size_t idx = (size_t)tok * HIDD + i;
        if (yf) *(float4*)(yf + idx) = o;
        if (yh) {
            __half h0, l0h, h1, l1h, h2, l2h, h3, l3h;
            split16(o.x, h0, l0h); split16(o.y, h1, l1h);
            split16(o.z, h2, l2h); split16(o.w, h3, l3h);
            *(__half2*)(yh + idx) = __halves2half2(h0, h1);
            *(__half2*)(yh + idx + 2) = __halves2half2(h2, h3);
            if (yl) {
                *(__half2*)(yl + idx) = __halves2half2(l0h, l1h);
                *(__half2*)(yl + idx + 2) = __halves2half2(l2h, l3h);
            }
        }
    }
}

// ---------------- weight cvt (wide, streaming) ----------------
__device__ __forceinline__ uint32_t packsplit_h(float a, float b) {
    __half2 t = __floats2half2_rn(a, b);
    return *(uint32_t*)&t;
}

__global__ void cvt16_k(const float* __restrict__ s, __half* __restrict__ h,
                        __half* __restrict__ l, size_t n) {
    size_t i = ((size_t)blockIdx.x * blockDim.x + threadIdx.x) * 8;
    if (i >= n) return;
    float4 v0 = __ldcs((const float4*)(s + i));
    float4 v1 = __ldcs((const float4*)(s + i + 4));
    float f[8] = {v0.x, v0.y, v0.z, v0.w, v1.x, v1.y, v1.z, v1.w};
    uint32_t hw[4], lw[4];
#pragma unroll
    for (int j = 0; j < 4; j++) {
        __half ha, la, hb, lb;
        split16(f[2 * j], ha, la); split16(f[2 * j + 1], hb, lb);
        __half2 hh = __halves2half2(ha, hb), ll = __halves2half2(la, lb);
        hw[j] = *(uint32_t*)&hh; lw[j] = *(uint32_t*)&ll;
    }
    __stcs((uint4*)(h + i), make_uint4(hw[0], hw[1], hw[2], hw[3]));
    __stcs((uint4*)(l + i), make_uint4(lw[0], lw[1], lw[2], lw[3]));
}

__global__ void cvt16h_k(const float* __restrict__ s, __half* __restrict__ h, size_t n) {
    size_t i = ((size_t)blockIdx.x * blockDim.x + threadIdx.x) * 8;
    if (i >= n) return;
    float4 v0 = __ldcs((const float4*)(s + i));
    float4 v1 = __ldcs((const float4*)(s + i + 4));
    __stcs((uint4*)(h + i),
           make_uint4(packsplit_h(v0.x, v0.y), packsplit_h(v0.z, v0.w),
                      packsplit_h(v1.x, v1.y), packsplit_h(v1.z, v1.w)));
}

__global__ void cvt16h_il_k(const float* __restrict__ s, __half* __restrict__ h,
                            size_t n, int off) {
    size_t i = ((size_t)blockIdx.x * blockDim.x + threadIdx.x) * 8;
    if (i >= n) return;
    size_t row = i / HIDD;
    size_t e = row / INTER, j = row % INTER;
    size_t dst = (e * 2 * INTER + 2 * j + (size_t)off) * HIDD + (i % HIDD);
    float4 v0 = __ldcs((const float4*)(s + i));
    float4 v1 = __ldcs((const float4*)(s + i + 4));
    __stcs((uint4*)(h + dst),
           make_uint4(packsplit_h(v0.x, v0.y), packsplit_h(v0.z, v0.w),
                      packsplit_h(v1.x, v1.y), packsplit_h(v1.z, v1.w)));
}

// ---------------- router ----------------
__global__ void zero_cnt_k() { if (threadIdx.x < NE) g_cnt[threadIdx.x] = 0; }

__global__ void router_k(const float* __restrict__ xn, const float* __restrict__ Wr) {
    const int tok = blockIdx.x;
    __shared__ float xs[HIDD];
    __shared__ float lg[NE];
    for (int i = threadIdx.x * 4; i < HIDD; i += blockDim.x * 4)
        *(float4*)(xs + i) = *(const float4*)(xn + (size_t)tok * HIDD + i);
    __syncthreads();
    const int w = threadIdx.x >> 5, lane = threadIdx.x & 31;
    const float* wr = Wr + (size_t)w * HIDD;
    float s = 0.f;
    for (int i = lane * 4; i < HIDD; i += 128) {
        float4 a = *(const float4*)(xs + i);
        float4 bb = *(const float4*)(wr + i);
        s += a.x * bb.x + a.y * bb.y + a.z * bb.z + a.w * bb.w;
    }
    for (int o = 16; o > 0; o >>= 1) s += __shfl_xor_sync(0xffffffffu, s, o);
    if (lane == 0) lg[w] = s;
    __syncthreads();
    if (threadIdx.x == 0) {
        float b1 = -INFINITY; int i1 = 0;
        for (int e = 0; e < NE; e++) if (lg[e] > b1) { b1 = lg[e]; i1 = e; }
        float b2 = -INFINITY; int i2 = (i1 == 0) ? 1 : 0;
        for (int e = 0; e < NE; e++) if (e != i1 && lg[e] > b2) { b2 = lg[e]; i2 = e; }
        float eo = expf(b2 - b1);
        float w1 = 1.f / (1.f + eo);
        float w2 = eo / (1.f + eo);
        int p1 = atomicAdd(&g_cnt[i1], 1);
        int p2 = atomicAdd(&g_cnt[i2], 1);
        g_gather[i1 * CAP + p1] = tok;
        g_gather[i2 * CAP + p2] = tok;
        g_slots[tok] = make_int2(i1 * CAP + p1, i2 * CAP + p2);
        g_wts[tok] = make_float2(w1, w2);
    }
}

// ---------------- final combine ----------------
__global__ void combine_k(const float* __restrict__ x2, float* __restrict__ out) {
    const int tok = blockIdx.x;
    const int2 sl = g_slots[tok];
    const float2 w = g_wts[tok];
    const float* y1 = g_yb + (size_t)sl.x * HIDD;
    const float* y2 = g_yb + (size_t)sl.y * HIDD;
    for (int i = threadIdx.x * 4; i < HIDD; i += blockDim.x * 4) {
        float4 a = *(const float4*)(x2 + (size_t)tok * HIDD + i);
        float4 b = *(const float4*)(y1 + i);
        float4 c = *(const float4*)(y2 + i);
        float4 o;
        o.x = a.x + w.x * b.x + w.y * c.x;
        o.y = a.y + w.x * b.y + w.y * c.y;
        o.z = a.z + w.x * b.z + w.y * c.z;
        o.w = a.w + w.x * b.w + w.y * c.w;
        *(float4*)(out + (size_t)tok * HIDD + i) = o;
    }
}

// ---------------- launch ----------------
extern "C" void kernel_launch(void* const* d_in, const int* in_sizes, int n_in,
                              void* d_out, int out_size) {
    (void)in_sizes; (void)n_in; (void)out_size;
    const float* x    = (const float*)d_in[0];
    const float* Wq   = (const float*)d_in[1];
    const float* Wk   = (const float*)d_in[2];
    const float* Wv   = (const float*)d_in[3];
    const float* Wo   = (const float*)d_in[4];
    const float* wln1 = (const float*)d_in[5];
    const float* wln2 = (const float*)d_in[6];
    const float* Wr   = (const float*)d_in[7];
    const float* Wg   = (const float*)d_in[8];
    const float* Wu   = (const float*)d_in[9];
    const float* Wd   = (const float*)d_in[10];
    float* out = (float*)d_out;

    void* p;
#define SYM(var, sym) cudaGetSymbolAddress(&p, sym); var = (decltype(var))p
    __half *xn1h, *xn1l, *qkvh, *qkvl, *atth, *attl, *wqkvh, *wqkvl, *woh, *wol;
    __half *xn2h, *wguh, *wdh, *acth;
    float *x2, *xn2, *yb;
    SYM(xn1h, g_xn1h); SYM(xn1l, g_xn1l);
    SYM(qkvh, g_qkvh); SYM(qkvl, g_qkvl);
    SYM(atth, g_atth); SYM(attl, g_attl);
    SYM(wqkvh, g_wqkvh); SYM(wqkvl, g_wqkvl);
    SYM(woh, g_woh); SYM(wol, g_wol);
    SYM(xn2h, g_xn2h); SYM(wguh, g_wguh); SYM(wdh, g_wdh);
    SYM(acth, g_acth);
    SYM(x2, g_x2); SYM(xn2, g_xn2); SYM(yb, g_yb);
#undef SYM

    // split: 4 arrays x 3 stages x 10,240B = 122,880B; single: 2 arrays x 4 stages = 81,920B
    const int split_smem  = 4 * 3 * HTILE * 2;
    const int single_smem = 2 * 4 * HTILE * 2;
    cudaFuncSetAttribute((const void*)hgemm<3, true,  false, false, true,  false>,
                         cudaFuncAttributeMaxDynamicSharedMemorySize, split_smem);
    cudaFuncSetAttribute((const void*)hgemm<3, true,  false, false, false, false>,
                         cudaFuncAttributeMaxDynamicSharedMemorySize, split_smem);
    cudaFuncSetAttribute((const void*)hgemm<4, false, true,  true,  false, true>,
                         cudaFuncAttributeMaxDynamicSharedMemorySize, single_smem);
    cudaFuncSetAttribute((const void*)hgemm<4, false, true,  false, false, false>,
                         cudaFuncAttributeMaxDynamicSharedMemorySize, single_smem);
    cudaFuncSetAttribute(flash_mma_k, cudaFuncAttributeMaxDynamicSharedMemorySize, FLASH_SMEM);

    const size_t HH = (size_t)HIDD * HIDD;
    const size_t EIH = (size_t)NE * INTER * HIDD;

    // weight prepass (wide streaming)
    cvt16_k<<<(unsigned)(HH / 2048), 256>>>(Wq, wqkvh, wqkvl, HH);
    cvt16_k<<<(unsigned)(HH / 2048), 256>>>(Wk, wqkvh + HH, wqkvl + HH, HH);
    cvt16_k<<<(unsigned)(HH / 2048), 256>>>(Wv, wqkvh + 2 * HH, wqkvl + 2 * HH, HH);
    cvt16_k<<<(unsigned)(HH / 2048), 256>>>(Wo, woh, wol, HH);
    cvt16h_il_k<<<(unsigned)(EIH / 2048), 256>>>(Wg, wguh, EIH, 0);
    cvt16h_il_k<<<(unsigned)(EIH / 2048), 256>>>(Wu, wguh, EIH, 1);
    cvt16h_k<<<(unsigned)(EIH / 2048), 256>>>(Wd, wdh, EIH);

    // 1) ln1 -> fp16 h/l
    rmsnorm_k<<<T_TOK, 256>>>(x, wln1, nullptr, xn1h, xn1l);
    // 2) fused QKV projection (split, fp16 h/l epilogue)
    hgemm<3, true, false, false, true, false><<<dim3(QKVW / HBN, T_TOK / HBM), 256, split_smem>>>(
        xn1h, xn1l, wqkvh, wqkvl, nullptr, nullptr, qkvh, qkvl, T_TOK, QKVW, HIDD, 0, 0, 0);
    // 3) flash attention
    flash_mma_k<<<dim3(SEQ / 64, NH, NB), 128, FLASH_SMEM>>>();
    // 4) O projection + residual (split, fp32 out)
    hgemm<3, true, false, false, false, false><<<dim3(HIDD / HBN, T_TOK / HBM), 256, split_smem>>>(
        atth, attl, woh, wol, x, x2, nullptr, nullptr, T_TOK, HIDD, HIDD, 0, 0, 0);
    // 5) ln2 -> fp32 (router) + fp16 (experts)
    rmsnorm_k<<<T_TOK, 256>>>(x2, wln2, xn2, xn2h, nullptr);
    // 6) routing
    zero_cnt_k<<<1, 32>>>();
    router_k<<<T_TOK, 256>>>(xn2, Wr);
    // 7) fused gate+up GEMM with SwiGLU epilogue -> acth (fp16)
    hgemm<4, false, true, true, false, true><<<dim3(2 * INTER / HBN, CAP / HBM, NE), 256, single_smem>>>(
        xn2h, nullptr, wguh, nullptr, nullptr, nullptr, acth, nullptr,
        0, 2 * INTER, HIDD, 0, (size_t)2 * INTER * HIDD, (size_t)CAP * INTER);
    // 8) down GEMM
    hgemm<4, false, true, false, false, false><<<dim3(HIDD / HBN, CAP / HBM, NE), 256, single_smem>>>(
        acth, nullptr, wdh, nullptr, nullptr, yb, nullptr, nullptr,
        0, HIDD, INTER, (size_t)CAP * INTER, (size_t)HIDD * INTER, (size_t)CAP * HIDD);
    // 9) combine + final residual
    combine_k<<<T_TOK, 256>>>(x2, out);
}

// round 13
// speedup vs baseline: 1.0172x; 1.0172x over previous
#include <cuda_runtime.h>
#include <cuda_fp16.h>
#include <math.h>
#include <stdint.h>

#define T_TOK 4096
#define HIDD  2048
#define NH    16
#define HD    128
#define SEQ   2048
#define NB    2
#define NE    8
#define INTER 4096
#define CAP   4096
#define EPS   1e-5f
#define QKVW  6144

// ---------------- scratch ----------------
__device__ __half g_xn1h[(size_t)T_TOK * HIDD];
__device__ __half g_xn1l[(size_t)T_TOK * HIDD];
__device__ __half g_qkvh[(size_t)T_TOK * QKVW];
__device__ __half g_qkvl[(size_t)T_TOK * QKVW];
__device__ __half g_atth[(size_t)T_TOK * HIDD];
__device__ __half g_attl[(size_t)T_TOK * HIDD];
__device__ float  g_x2  [(size_t)T_TOK * HIDD];
__device__ float  g_xn2 [(size_t)T_TOK * HIDD];
__device__ __half g_xn2h[(size_t)T_TOK * HIDD];
__device__ __half g_acth[(size_t)NE * CAP * INTER];
__device__ float  g_yb  [(size_t)NE * CAP * HIDD];
__device__ __half g_wqkvh[(size_t)QKVW * HIDD];
__device__ __half g_wqkvl[(size_t)QKVW * HIDD];
__device__ __half g_woh[(size_t)HIDD * HIDD];
__device__ __half g_wol[(size_t)HIDD * HIDD];
__device__ __half g_wguh[(size_t)NE * 2 * INTER * HIDD];  // interleaved gate/up rows
__device__ __half g_wdh[(size_t)NE * HIDD * INTER];
__device__ int    g_cnt[NE];
__device__ int    g_gather[NE * CAP];
__device__ int2   g_slots[T_TOK];
__device__ float2 g_wts[T_TOK];

// ---------------- helpers ----------------
__device__ __forceinline__ void mma16(float* c, const uint32_t* a, uint32_t b0, uint32_t b1) {
    asm volatile(
        "mma.sync.aligned.m16n8k16.row.col.f32.f16.f16.f32 "
        "{%0,%1,%2,%3}, {%4,%5,%6,%7}, {%8,%9}, {%0,%1,%2,%3};"
        : "+f"(c[0]), "+f"(c[1]), "+f"(c[2]), "+f"(c[3])
        : "r"(a[0]), "r"(a[1]), "r"(a[2]), "r"(a[3]), "r"(b0), "r"(b1));
}
__device__ __forceinline__ void ldm_x4(uint32_t* r, uint32_t saddr) {
    asm volatile("ldmatrix.sync.aligned.m8n8.x4.shared.b16 {%0,%1,%2,%3}, [%4];"
                 : "=r"(r[0]), "=r"(r[1]), "=r"(r[2]), "=r"(r[3]) : "r"(saddr));
}
__device__ __forceinline__ void cp_async16(void* smem, const void* gmem) {
    uint32_t s = (uint32_t)__cvta_generic_to_shared(smem);
    asm volatile("cp.async.cg.shared.global [%0], [%1], 16;\n" :: "r"(s), "l"(gmem));
}
__device__ __forceinline__ void cp_commit() { asm volatile("cp.async.commit_group;\n"); }
__device__ __forceinline__ void cp_wait0()  { asm volatile("cp.async.wait_group 0;\n"); }
__device__ __forceinline__ uint32_t ld32s(const __half* p) { return *(const uint32_t*)p; }
__device__ __forceinline__ void split16(float x, __half& h, __half& l) {
    h = __float2half_rn(x);
    l = __float2half_rn(x - __half2float(h));
}

// =========================================================================
// unified fp16 GEMM (R10 config: 2-stage, ldmatrix, fused SwiGLU)
// =========================================================================
#define HBM 128
#define HBN 128
#define HBK 32
#define HS  40
#define HTILE (128 * HS)

template <bool SPLIT, bool MOE, bool GATHER, bool EPI16, bool SWIGLU>
__global__ __launch_bounds__(256)
void hgemm(const __half* __restrict__ Ah, const __half* __restrict__ Al,
           const __half* __restrict__ Bh, const __half* __restrict__ Bl,
           const float* __restrict__ resid, float* __restrict__ Cf,
           __half* __restrict__ Ch, __half* __restrict__ Cl,
           int M, int N, int K, size_t aes, size_t bes, size_t ces) {
    extern __shared__ __half hsm[];
    __shared__ int rows_s[HBM];
    const int t = threadIdx.x, lane = t & 31, wid = t >> 5;
    const int lq = lane >> 2, lr = lane & 3;
    const int lrow16 = lane & 15, lsel = lane >> 4;
    const int rb = (wid >> 2) * 64, cb = (wid & 3) * 32;
    const int bm = blockIdx.y * HBM, bn = blockIdx.x * HBN;

    if (MOE) {
        int e = blockIdx.z;
        M = g_cnt[e];
        if (bm >= M) return;
        Ah += (size_t)e * aes;
        Bh += (size_t)e * bes;
        if (SWIGLU) Ch += (size_t)e * ces; else Cf += (size_t)e * ces;
        if (GATHER && t < HBM) {
            int r = bm + t;
            if (r >= M) r = M - 1;
            rows_s[t] = g_gather[e * CAP + r];
        }
        if (GATHER) __syncthreads();
    }

    const uint32_t sbase = (uint32_t)__cvta_generic_to_shared(hsm);
    const int IA_H = 0, IA_L = 1, IB_H = SPLIT ? 2 : 1, IB_L = 3;
    auto tgen = [&](int arr, int buf) { return hsm + (size_t)(arr * 2 + buf) * HTILE; };
    auto tsh  = [&](int arr, int buf) { return sbase + (uint32_t)(arr * 2 + buf) * HTILE * 2; };

    float acc[4][4][4];
#pragma unroll
    for (int i = 0; i < 4; i++)
#pragma unroll
        for (int j = 0; j < 4; j++)
#pragma unroll
            for (int f = 0; f < 4; f++) acc[i][j][f] = 0.f;

    int lrow[2], lsg[2];
    size_t aoff[2], boff[2];
#pragma unroll
    for (int i = 0; i < 2; i++) {
        int slot = t + 256 * i;
        lrow[i] = slot >> 2; lsg[i] = (slot & 3) * 8;
        size_t ar = GATHER ? (size_t)rows_s[lrow[i]] : (size_t)(bm + lrow[i]);
        aoff[i] = ar * K + lsg[i];
        boff[i] = (size_t)(bn + lrow[i]) * K + lsg[i];
    }

    auto issue = [&](int c, int buf) {
        const int k0 = c * HBK;
#pragma unroll
        for (int i = 0; i < 2; i++) {
            cp_async16(tgen(IA_H, buf) + lrow[i] * HS + lsg[i], Ah + aoff[i] + k0);
            cp_async16(tgen(IB_H, buf) + lrow[i] * HS + lsg[i], Bh + boff[i] + k0);
            if (SPLIT) {
                cp_async16(tgen(IA_L, buf) + lrow[i] * HS + lsg[i], Al + aoff[i] + k0);
                cp_async16(tgen(IB_L, buf) + lrow[i] * HS + lsg[i], Bl + boff[i] + k0);
            }
        }
        cp_commit();
    };

    auto compute = [&](int buf) {
        const uint32_t tAh = tsh(IA_H, buf), tBh = tsh(IB_H, buf);
        const uint32_t tAl = tsh(IA_L, buf), tBl = tsh(IB_L, buf);
#pragma unroll
        for (int ks = 0; ks < 2; ks++) {
            const int k0 = ks * 16;
            uint32_t ah[4][4], al[4][4], bh[4][2], bl[4][2];
#pragma unroll
            for (int mt = 0; mt < 4; mt++) {
                uint32_t off = (uint32_t)(((rb + mt * 16 + lrow16) * HS + k0 + lsel * 8) * 2);
                ldm_x4(ah[mt], tAh + off);
                if (SPLIT) ldm_x4(al[mt], tAl + off);
            }
#pragma unroll
            for (int np = 0; np < 2; np++) {
                uint32_t off = (uint32_t)(((cb + np * 16 + lrow16) * HS + k0 + lsel * 8) * 2);
                uint32_t r[4];
                ldm_x4(r, tBh + off);
                bh[2 * np][0] = r[0]; bh[2 * np][1] = r[2];
                bh[2 * np + 1][0] = r[1]; bh[2 * np + 1][1] = r[3];
                if (SPLIT) {
                    ldm_x4(r, tBl + off);
                    bl[2 * np][0] = r[0]; bl[2 * np][1] = r[2];
                    bl[2 * np + 1][0] = r[1]; bl[2 * np + 1][1] = r[3];
                }
            }
#pragma unroll
            for (int mt = 0; mt < 4; mt++)
#pragma unroll
                for (int nt = 0; nt < 4; nt++) {
                    mma16(acc[mt][nt], ah[mt], bh[nt][0], bh[nt][1]);
                    if (SPLIT) {
                        mma16(acc[mt][nt], ah[mt], bl[nt][0], bl[nt][1]);
                        mma16(acc[mt][nt], al[mt], bh[nt][0], bh[nt][1]);
                    }
                }
        }
    };

    const int nk = K / HBK;
    issue(0, 0);
    cp_wait0();
    __syncthreads();
    for (int c = 0; c < nk; c++) {
        const int cur = c & 1;
        if (c + 1 < nk) issue(c + 1, cur ^ 1);
        compute(cur);
        if (c + 1 < nk) cp_wait0();
        __syncthreads();
    }

#pragma unroll
    for (int mt = 0; mt < 4; mt++)
#pragma unroll
        for (int nt = 0; nt < 4; nt++) {
            int r0g = bm + rb + mt * 16 + lq;
            int r1g = r0g + 8;
            int c0 = bn + cb + nt * 8 + lr * 2;
            if (SWIGLU) {
                int oc = c0 >> 1;
                if (r0g < M) {
                    float g = acc[mt][nt][0], u = acc[mt][nt][1];
                    Ch[(size_t)r0g * INTER + oc] =
                        __float2half_rn(g / (1.f + __expf(-g)) * u);
                }
                if (r1g < M) {
                    float g = acc[mt][nt][2], u = acc[mt][nt][3];
                    Ch[(size_t)r1g * INTER + oc] =
                        __float2half_rn(g / (1.f + __expf(-g)) * u);
                }
            } else if (EPI16) {
                __half h0, l0, h1, l1;
                split16(acc[mt][nt][0], h0, l0); split16(acc[mt][nt][1], h1, l1);
                *(__half2*)(Ch + (size_t)r0g * N + c0) = __halves2half2(h0, h1);
                *(__half2*)(Cl + (size_t)r0g * N + c0) = __halves2half2(l0, l1);
                split16(acc[mt][nt][2], h0, l0); split16(acc[mt][nt][3], h1, l1);
                *(__half2*)(Ch + (size_t)r1g * N + c0) = __halves2half2(h0, h1);
                *(__half2*)(Cl + (size_t)r1g * N + c0) = __halves2half2(l0, l1);
            } else {
                if (!MOE || r0g < M) {
                    float2 v0 = make_float2(acc[mt][nt][0], acc[mt][nt][1]);
                    if (resid) {
                        v0.x += resid[(size_t)r0g * N + c0];
                        v0.y += resid[(size_t)r0g * N + c0 + 1];
                    }
                    *(float2*)(Cf + (size_t)r0g * N + c0) = v0;
                }
                if (!MOE || r1g < M) {
                    float2 v1 = make_float2(acc[mt][nt][2], acc[mt][nt][3]);
                    if (resid) {
                        v1.x += resid[(size_t)r1g * N + c0];
                        v1.y += resid[(size_t)r1g * N + c0 + 1];
                    }
                    *(float2*)(Cf + (size_t)r1g * N + c0) = v1;
                }
            }
        }
}

// =========================================================================
// flash attention: fp16-split mma, causal, 64q x 64k tiles, 4 warps
// =========================================================================
#define QS 136
#define VS 72
#define FLASH_SMEM ((4 * 64 * QS + 2 * 128 * VS) * 2)

__global__ __launch_bounds__(128)
void flash_mma_k() {
    extern __shared__ __half fsm[];
    __half* Qh  = fsm;
    __half* Ql  = Qh + 64 * QS;
    __half* Kh  = Ql + 64 * QS;
    __half* Kl  = Kh + 64 * QS;
    __half* Vth = Kl + 64 * QS;
    __half* Vtl = Vth + 128 * VS;

    const int qt = blockIdx.x, head = blockIdx.y, b = blockIdx.z;
    const int t = threadIdx.x, wid = t >> 5, lane = t & 31;
    const int lq = lane >> 2, lr = lane & 3;
    const int wr = wid * 16;
    const float scale = 0.08838834764831845f;
    const size_t base = (size_t)b * SEQ * QKVW;
    const size_t qoff = (size_t)head * HD;
    const size_t koff = 2048 + qoff, voff = 4096 + qoff;

    for (int i = t; i < 64 * 16; i += 128) {
        int r = i >> 4, sg = (i & 15) * 8;
        size_t g = base + (size_t)(qt * 64 + r) * QKVW + qoff + sg;
        *(uint4*)(Qh + r * QS + sg) = *(const uint4*)(g_qkvh + g);
        *(uint4*)(Ql + r * QS + sg) = *(const uint4*)(g_qkvl + g);
    }

    float out[16][4];
#pragma unroll
    for (int i = 0; i < 16; i++)
#pragma unroll
        for (int j = 0; j < 4; j++) out[i][j] = 0.f;
    float m0 = -INFINITY, m1 = -INFINITY, l0 = 0.f, l1 = 0.f;

    for (int kt = 0; kt <= qt; kt++) {
        __syncthreads();
        for (int i = t; i < 64 * 16; i += 128) {
            int r = i >> 4, sg = (i & 15) * 8;
            size_t g = base + (size_t)(kt * 64 + r) * QKVW + koff + sg;
            *(uint4*)(Kh + r * QS + sg) = *(const uint4*)(g_qkvh + g);
            *(uint4*)(Kl + r * QS + sg) = *(const uint4*)(g_qkvl + g);
        }
        for (int i = t; i < 64 * 64; i += 128) {
            int r = i >> 6, dp = i & 63;
            size_t g = base + (size_t)(kt * 64 + r) * QKVW + voff + dp * 2;
            __half2 vh = *(const __half2*)(g_qkvh + g);
            __half2 vl = *(const __half2*)(g_qkvl + g);
            Vth[(2 * dp) * VS + r]     = __low2half(vh);
            Vth[(2 * dp + 1) * VS + r] = __high2half(vh);
            Vtl[(2 * dp) * VS + r]     = __low2half(vl);
            Vtl[(2 * dp + 1) * VS + r] = __high2half(vl);
        }
        __syncthreads();

        float s[8][4];
#pragma unroll
        for (int i = 0; i < 8; i++)
#pragma unroll
            for (int j = 0; j < 4; j++) s[i][j] = 0.f;

        for (int kc = 0; kc < 8; kc++) {
            uint32_t ah[4], al[4];
            const __half* qp = Qh + (wr + lq) * QS + kc * 16 + lr * 2;
            const __half* ql = Ql + (wr + lq) * QS + kc * 16 + lr * 2;
            ah[0] = ld32s(qp);     ah[1] = ld32s(qp + 8 * QS);
            ah[2] = ld32s(qp + 8); ah[3] = ld32s(qp + 8 * QS + 8);
            al[0] = ld32s(ql);     al[1] = ld32s(ql + 8 * QS);
            al[2] = ld32s(ql + 8); al[3] = ld32s(ql + 8 * QS + 8);
#pragma unroll
            for (int nt = 0; nt < 8; nt++) {
                const __half* kp = Kh + (nt * 8 + lq) * QS + kc * 16 + lr * 2;
                const __half* kl = Kl + (nt * 8 + lq) * QS + kc * 16 + lr * 2;
                uint32_t bh0 = ld32s(kp), bh1 = ld32s(kp + 8);
                uint32_t bl0 = ld32s(kl), bl1 = ld32s(kl + 8);
                mma16(s[nt], ah, bh0, bh1);
                mma16(s[nt], ah, bl0, bl1);
                mma16(s[nt], al, bh0, bh1);
            }
        }

        const bool diag = (kt == qt);
#pragma unroll
        for (int nt = 0; nt < 8; nt++)
#pragma unroll
            for (int cc = 0; cc < 4; cc++) {
                float v = s[nt][cc] * scale;
                if (diag) {
                    int col = nt * 8 + lr * 2 + (cc & 1);
                    int row = wr + lq + ((cc >= 2) ? 8 : 0);
                    if (col > row) v = -INFINITY;
                }
                s[nt][cc] = v;
            }

        float mx0 = m0, mx1 = m1;
#pragma unroll
        for (int nt = 0; nt < 8; nt++) {
            mx0 = fmaxf(mx0, fmaxf(s[nt][0], s[nt][1]));
            mx1 = fmaxf(mx1, fmaxf(s[nt][2], s[nt][3]));
        }
        mx0 = fmaxf(mx0, __shfl_xor_sync(0xffffffffu, mx0, 1));
        mx0 = fmaxf(mx0, __shfl_xor_sync(0xffffffffu, mx0, 2));
        mx1 = fmaxf(mx1, __shfl_xor_sync(0xffffffffu, mx1, 1));
        mx1 = fmaxf(mx1, __shfl_xor_sync(0xffffffffu, mx1, 2));
        float a0 = __expf(m0 - mx0), a1 = __expf(m1 - mx1);
        m0 = mx0; m1 = mx1;
        float sum0 = 0.f, sum1 = 0.f;
#pragma unroll
        for (int nt = 0; nt < 8; nt++) {
            s[nt][0] = __expf(s[nt][0] - mx0);
            s[nt][1] = __expf(s[nt][1] - mx0);
            s[nt][2] = __expf(s[nt][2] - mx1);
            s[nt][3] = __expf(s[nt][3] - mx1);
            sum0 += s[nt][0] + s[nt][1];
            sum1 += s[nt][2] + s[nt][3];
        }
        sum0 += __shfl_xor_sync(0xffffffffu, sum0, 1);
        sum0 += __shfl_xor_sync(0xffffffffu, sum0, 2);
        sum1 += __shfl_xor_sync(0xffffffffu, sum1, 1);
        sum1 += __shfl_xor_sync(0xffffffffu, sum1, 2);
        l0 = l0 * a0 + sum0;
        l1 = l1 * a1 + sum1;

#pragma unroll
        for (int nt = 0; nt < 16; nt++) {
            out[nt][0] *= a0; out[nt][1] *= a0;
            out[nt][2] *= a1; out[nt][3] *= a1;
        }

#pragma unroll
        for (int kc = 0; kc < 4; kc++) {
            const int t0 = 2 * kc, t1 = 2 * kc + 1;
            uint32_t ph[4], pl[4];
            {
                __half2 h, l;
                h = __floats2half2_rn(s[t0][0], s[t0][1]);
                l = __floats2half2_rn(s[t0][0] - __low2float(h), s[t0][1] - __high2float(h));
                ph[0] = *(uint32_t*)&h; pl[0] = *(uint32_t*)&l;
                h = __floats2half2_rn(s[t0][2], s[t0][3]);
                l = __floats2half2_rn(s[t0][2] - __low2float(h), s[t0][3] - __high2float(h));
                ph[1] = *(uint32_t*)&h; pl[1] = *(uint32_t*)&l;
                h = __floats2half2_rn(s[t1][0], s[t1][1]);
                l = __floats2half2_rn(s[t1][0] - __low2float(h), s[t1][1] - __high2float(h));
                ph[2] = *(uint32_t*)&h; pl[2] = *(uint32_t*)&l;
                h = __floats2half2_rn(s[t1][2], s[t1][3]);
                l = __floats2half2_rn(s[t1][2] - __low2float(h), s[t1][3] - __high2float(h));
                ph[3] = *(uint32_t*)&h; pl[3] = *(uint32_t*)&l;
            }
#pragma unroll
            for (int nt = 0; nt < 16; nt++) {
                const __half* vp = Vth + (nt * 8 + lq) * VS + kc * 16 + lr * 2;
                const __half* vl = Vtl + (nt * 8 + lq) * VS + kc * 16 + lr * 2;
                uint32_t bh0 = ld32s(vp), bh1 = ld32s(vp + 8);
                uint32_t bl0 = ld32s(vl), bl1 = ld32s(vl + 8);
                mma16(out[nt], ph, bh0, bh1);
                mma16(out[nt], ph, bl0, bl1);
                mma16(out[nt], pl, bh0, bh1);
            }
        }
    }

    const float inv0 = 1.f / l0, inv1 = 1.f / l1;
    const int row0 = qt * 64 + wr + lq;
    const size_t o0 = ((size_t)b * SEQ + row0) * HIDD + head * HD;
    const size_t o1 = o0 + 8 * HIDD;
#pragma unroll
    for (int nt = 0; nt < 16; nt++) {
        int c = nt * 8 + lr * 2;
        __half h0, lo0, h1, lo1;
        split16(out[nt][0] * inv0, h0, lo0);
        split16(out[nt][1] * inv0, h1, lo1);
        *(__half2*)(g_atth + o0 + c) = __halves2half2(h0, h1);
        *(__half2*)(g_attl + o0 + c) = __halves2half2(lo0, lo1);
        split16(out[nt][2] * inv1, h0, lo0);
        split16(out[nt][3] * inv1, h1, lo1);
        *(__half2*)(g_atth + o1 + c) = __halves2half2(h0, h1);
        *(__half2*)(g_attl + o1 + c) = __halves2half2(lo0, lo1);
    }
}

// ---------------- RMSNorm ----------------
__global__ void rmsnorm_k(const float* __restrict__ x, const float* __restrict__ w,
                          float* __restrict__ yf, __half* __restrict__ yh,
                          __half* __restrict__ yl) {
    int tok = blockIdx.x;
    const float* xr = x + (size_t)tok * HIDD;
    float s = 0.f;
    for (int i = threadIdx.x * 4; i < HIDD; i += blockDim.x * 4) {
        float4 v = *(const float4*)(xr + i);
        s += v.x * v.x + v.y * v.y + v.z * v.z + v.w * v.w;
    }
    __shared__ float red[32];
    for (int o = 16; o > 0; o >>= 1) s += __shfl_xor_sync(0xffffffffu, s, o);
    if ((threadIdx.x & 31) == 0) red[threadIdx.x >> 5] = s;
    __syncthreads();
    if (threadIdx.x < 32) {
        float v = (threadIdx.x < (blockDim.x >> 5)) ? red[threadIdx.x] : 0.f;
        for (int o = 4; o > 0; o >>= 1) v += __shfl_xor_sync(0xffffffffu, v, o);
        if (threadIdx.x == 0) red[0] = rsqrtf(v / (float)HIDD + EPS);
    }
    __syncthreads();
    float sc = red[0];
    for (int i = threadIdx.x * 4; i < HIDD; i += blockDim.x * 4) {
        float4 v = *(const float4*)(xr + i);
        float4 wv = *(const float4*)(w + i);
        float4 o;
        o.x = v.x * sc * wv.x; o.y = v.y * sc * wv.y;
        o.z = v.z * sc * wv.z; o.w = v.w * sc * wv.w;
        size_t idx = (size_t)tok * HIDD + i;
        if (yf) *(float4*)(yf + idx) = o;
        if (yh) {
            __half h0, l0h, h1, l1h, h2, l2h, h3, l3h;
            split16(o.x, h0, l0h); split16(o.y, h1, l1h);
            split16(o.z, h2, l2h); split16(o.w, h3, l3h);
            *(__half2*)(yh + idx) = __halves2half2(h0, h1);
            *(__half2*)(yh + idx + 2) = __halves2half2(h2, h3);
            if (yl) {
                *(__half2*)(yl + idx) = __halves2half2(l0h, l1h);
                *(__half2*)(yl + idx + 2) = __halves2half2(l2h, l3h);
            }
        }
    }
}

// ---------------- weight cvt (wide, streaming) ----------------
__device__ __forceinline__ uint32_t packsplit_h(float a, float b) {
    __half2 t = __floats2half2_rn(a, b);
    return *(uint32_t*)&t;
}

__global__ void cvt16_k(const float* __restrict__ s, __half* __restrict__ h,
                        __half* __restrict__ l, size_t n) {
    size_t i = ((size_t)blockIdx.x * blockDim.x + threadIdx.x) * 8;
    if (i >= n) return;
    float4 v0 = __ldcs((const float4*)(s + i));
    float4 v1 = __ldcs((const float4*)(s + i + 4));
    float f[8] = {v0.x, v0.y, v0.z, v0.w, v1.x, v1.y, v1.z, v1.w};
    uint32_t hw[4], lw[4];
#pragma unroll
    for (int j = 0; j < 4; j++) {
        __half ha, la, hb, lb;
        split16(f[2 * j], ha, la); split16(f[2 * j + 1], hb, lb);
        __half2 hh = __halves2half2(ha, hb), ll = __halves2half2(la, lb);
        hw[j] = *(uint32_t*)&hh; lw[j] = *(uint32_t*)&ll;
    }
    __stcs((uint4*)(h + i), make_uint4(hw[0], hw[1], hw[2], hw[3]));
    __stcs((uint4*)(l + i), make_uint4(lw[0], lw[1], lw[2], lw[3]));
}

__global__ void cvt16h_k(const float* __restrict__ s, __half* __restrict__ h, size_t n) {
    size_t i = ((size_t)blockIdx.x * blockDim.x + threadIdx.x) * 8;
    if (i >= n) return;
    float4 v0 = __ldcs((const float4*)(s + i));
    float4 v1 = __ldcs((const float4*)(s + i + 4));
    __stcs((uint4*)(h + i),
           make_uint4(packsplit_h(v0.x, v0.y), packsplit_h(v0.z, v0.w),
                      packsplit_h(v1.x, v1.y), packsplit_h(v1.z, v1.w)));
}

__global__ void cvt16h_il_k(const float* __restrict__ s, __half* __restrict__ h,
                            size_t n, int off) {
    size_t i = ((size_t)blockIdx.x * blockDim.x + threadIdx.x) * 8;
    if (i >= n) return;
    size_t row = i / HIDD;
    size_t e = row / INTER, j = row % INTER;
    size_t dst = (e * 2 * INTER + 2 * j + (size_t)off) * HIDD + (i % HIDD);
    float4 v0 = __ldcs((const float4*)(s + i));
    float4 v1 = __ldcs((const float4*)(s + i + 4));
    __stcs((uint4*)(h + dst),
           make_uint4(packsplit_h(v0.x, v0.y), packsplit_h(v0.z, v0.w),
                      packsplit_h(v1.x, v1.y), packsplit_h(v1.z, v1.w)));
}

// ---------------- router ----------------
__global__ void zero_cnt_k() { if (threadIdx.x < NE) g_cnt[threadIdx.x] = 0; }

__global__ void router_k(const float* __restrict__ xn, const float* __restrict__ Wr) {
    const int tok = blockIdx.x;
    __shared__ float xs[HIDD];
    __shared__ float lg[NE];
    for (int i = threadIdx.x * 4; i < HIDD; i += blockDim.x * 4)
        *(float4*)(xs + i) = *(const float4*)(xn + (size_t)tok * HIDD + i);
    __syncthreads();
    const int w = threadIdx.x >> 5, lane = threadIdx.x & 31;
    const float* wr = Wr + (size_t)w * HIDD;
    float s = 0.f;
    for (int i = lane * 4; i < HIDD; i += 128) {
        float4 a = *(const float4*)(xs + i);
        float4 bb = *(const float4*)(wr + i);
        s += a.x * bb.x + a.y * bb.y + a.z * bb.z + a.w * bb.w;
    }
    for (int o = 16; o > 0; o >>= 1) s += __shfl_xor_sync(0xffffffffu, s, o);
    if (lane == 0) lg[w] = s;
    __syncthreads();
    if (threadIdx.x == 0) {
        float b1 = -INFINITY; int i1 = 0;
        for (int e = 0; e < NE; e++) if (lg[e] > b1) { b1 = lg[e]; i1 = e; }
        float b2 = -INFINITY; int i2 = (i1 == 0) ? 1 : 0;
        for (int e = 0; e < NE; e++) if (e != i1 && lg[e] > b2) { b2 = lg[e]; i2 = e; }
        float eo = expf(b2 - b1);
        float w1 = 1.f / (1.f + eo);
        float w2 = eo / (1.f + eo);
        int p1 = atomicAdd(&g_cnt[i1], 1);
        int p2 = atomicAdd(&g_cnt[i2], 1);
        g_gather[i1 * CAP + p1] = tok;
        g_gather[i2 * CAP + p2] = tok;
        g_slots[tok] = make_int2(i1 * CAP + p1, i2 * CAP + p2);
        g_wts[tok] = make_float2(w1, w2);
    }
}

// ---------------- final combine ----------------
__global__ void combine_k(const float* __restrict__ x2, float* __restrict__ out) {
    const int tok = blockIdx.x;
    const int2 sl = g_slots[tok];
    const float2 w = g_wts[tok];
    const float* y1 = g_yb + (size_t)sl.x * HIDD;
    const float* y2 = g_yb + (size_t)sl.y * HIDD;
    for (int i = threadIdx.x * 4; i < HIDD; i += blockDim.x * 4) {
        float4 a = *(const float4*)(x2 + (size_t)tok * HIDD + i);
        float4 b = *(const float4*)(y1 + i);
        float4 c = *(const float4*)(y2 + i);
        float4 o;
        o.x = a.x + w.x * b.x + w.y * c.x;
        o.y = a.y + w.x * b.y + w.y * c.y;
        o.z = a.z + w.x * b.z + w.y * c.z;
        o.w = a.w + w.x * b.w + w.y * c.w;
        *(float4*)(out + (size_t)tok * HIDD + i) = o;
    }
}

// ---------------- launch ----------------
extern "C" void kernel_launch(void* const* d_in, const int* in_sizes, int n_in,
                              void* d_out, int out_size) {
    (void)in_sizes; (void)n_in; (void)out_size;
    const float* x    = (const float*)d_in[0];
    const float* Wq   = (const float*)d_in[1];
    const float* Wk   = (const float*)d_in[2];
    const float* Wv   = (const float*)d_in[3];
    const float* Wo   = (const float*)d_in[4];
    const float* wln1 = (const float*)d_in[5];
    const float* wln2 = (const float*)d_in[6];
    const float* Wr   = (const float*)d_in[7];
    const float* Wg   = (const float*)d_in[8];
    const float* Wu   = (const float*)d_in[9];
    const float* Wd   = (const float*)d_in[10];
    float* out = (float*)d_out;

    void* p;
#define SYM(var, sym) cudaGetSymbolAddress(&p, sym); var = (decltype(var))p
    __half *xn1h, *xn1l, *qkvh, *qkvl, *atth, *attl, *wqkvh, *wqkvl, *woh, *wol;
    __half *xn2h, *wguh, *wdh, *acth;
    float *x2, *xn2, *yb;
    SYM(xn1h, g_xn1h); SYM(xn1l, g_xn1l);
    SYM(qkvh, g_qkvh); SYM(qkvl, g_qkvl);
    SYM(atth, g_atth); SYM(attl, g_attl);
    SYM(wqkvh, g_wqkvh); SYM(wqkvl, g_wqkvl);
    SYM(woh, g_woh); SYM(wol, g_wol);
    SYM(xn2h, g_xn2h); SYM(wguh, g_wguh); SYM(wdh, g_wdh);
    SYM(acth, g_acth);
    SYM(x2, g_x2); SYM(xn2, g_xn2); SYM(yb, g_yb);
#undef SYM

    // side stream + events (created once, outside any capture; reused thereafter)
    static cudaStream_t s2 = nullptr;
    static cudaEvent_t ev_fork = nullptr, ev_wo = nullptr, ev_moe = nullptr;
    if (s2 == nullptr) {
        cudaStreamCreateWithFlags(&s2, cudaStreamNonBlocking);
        cudaEventCreateWithFlags(&ev_fork, cudaEventDisableTiming);
        cudaEventCreateWithFlags(&ev_wo, cudaEventDisableTiming);
        cudaEventCreateWithFlags(&ev_moe, cudaEventDisableTiming);
    }

    const int split_smem  = 8 * HTILE * 2;   // 81920
    const int single_smem = 4 * HTILE * 2;   // 40960
    cudaFuncSetAttribute((const void*)hgemm<true,  false, false, true,  false>,
                         cudaFuncAttributeMaxDynamicSharedMemorySize, split_smem);
    cudaFuncSetAttribute((const void*)hgemm<true,  false, false, false, false>,
                         cudaFuncAttributeMaxDynamicSharedMemorySize, split_smem);
    cudaFuncSetAttribute((const void*)hgemm<false, true,  true,  false, true>,
                         cudaFuncAttributeMaxDynamicSharedMemorySize, single_smem);
    cudaFuncSetAttribute((const void*)hgemm<false, true,  false, false, false>,
                         cudaFuncAttributeMaxDynamicSharedMemorySize, single_smem);
    cudaFuncSetAttribute(flash_mma_k, cudaFuncAttributeMaxDynamicSharedMemorySize, FLASH_SMEM);

    const size_t HH = (size_t)HIDD * HIDD;
    const size_t EIH = (size_t)NE * INTER * HIDD;

    // ---- fork side stream: Wo + MoE weight conversions overlap QKV/flash ----
    cudaEventRecord(ev_fork, 0);
    cudaStreamWaitEvent(s2, ev_fork, 0);
    cvt16_k<<<(unsigned)(HH / 2048), 256, 0, s2>>>(Wo, woh, wol, HH);
    cudaEventRecord(ev_wo, s2);
    cvt16h_il_k<<<(unsigned)(EIH / 2048), 256, 0, s2>>>(Wg, wguh, EIH, 0);
    cvt16h_il_k<<<(unsigned)(EIH / 2048), 256, 0, s2>>>(Wu, wguh, EIH, 1);
    cvt16h_k<<<(unsigned)(EIH / 2048), 256, 0, s2>>>(Wd, wdh, EIH);
    cudaEventRecord(ev_moe, s2);

    // ---- main stream: QKV weight cvts + attention path ----
    cvt16_k<<<(unsigned)(HH / 2048), 256>>>(Wq, wqkvh, wqkvl, HH);
    cvt16_k<<<(unsigned)(HH / 2048), 256>>>(Wk, wqkvh + HH, wqkvl + HH, HH);
    cvt16_k<<<(unsigned)(HH / 2048), 256>>>(Wv, wqkvh + 2 * HH, wqkvl + 2 * HH, HH);

    // 1) ln1 -> fp16 h/l
    rmsnorm_k<<<T_TOK, 256>>>(x, wln1, nullptr, xn1h, xn1l);
    // 2) fused QKV projection (split, fp16 h/l epilogue)
    hgemm<true, false, false, true, false><<<dim3(QKVW / HBN, T_TOK / HBM), 256, split_smem>>>(
        xn1h, xn1l, wqkvh, wqkvl, nullptr, nullptr, qkvh, qkvl, T_TOK, QKVW, HIDD, 0, 0, 0);
    // 3) flash attention
    flash_mma_k<<<dim3(SEQ / 64, NH, NB), 128, FLASH_SMEM>>>();
    // 4) O projection + residual (needs Wo cvt from side stream)
    cudaStreamWaitEvent(0, ev_wo, 0);
    hgemm<true, false, false, false, false><<<dim3(HIDD / HBN, T_TOK / HBM), 256, split_smem>>>(
        atth, attl, woh, wol, x, x2, nullptr, nullptr, T_TOK, HIDD, HIDD, 0, 0, 0);
    // 5) ln2 -> fp32 (router) + fp16 (experts)
    rmsnorm_k<<<T_TOK, 256>>>(x2, wln2, xn2, xn2h, nullptr);
    // 6) routing
    zero_cnt_k<<<1, 32>>>();
    router_k<<<T_TOK, 256>>>(xn2, Wr);
    // 7) fused gate+up GEMM with SwiGLU epilogue (needs MoE weight cvts)
    cudaStreamWaitEvent(0, ev_moe, 0);
    hgemm<false, true, true, false, true><<<dim3(2 * INTER / HBN, CAP / HBM, NE), 256, single_smem>>>(
        xn2h, nullptr, wguh, nullptr, nullptr, nullptr, acth, nullptr,
        0, 2 * INTER, HIDD, 0, (size_t)2 * INTER * HIDD, (size_t)CAP * INTER);
    // 8) down GEMM
    hgemm<false, true, false, false, false><<<dim3(HIDD / HBN, CAP / HBM, NE), 256, single_smem>>>(
        acth, nullptr, wdh, nullptr, nullptr, yb, nullptr, nullptr,
        0, HIDD, INTER, (size_t)CAP * INTER, (size_t)HIDD * INTER, (size_t)CAP * HIDD);
    // 9) combine + final residual
    combine_k<<<T_TOK, 256>>>(x2, out);
}

// round 15
// speedup vs baseline: 1.1540x; 1.1344x over previous
#include <cuda_runtime.h>
#include <cuda_fp16.h>
#include <math.h>
#include <stdint.h>

#define T_TOK 4096
#define HIDD  2048
#define NH    16
#define HD    128
#define SEQ   2048
#define NB    2
#define NE    8
#define INTER 4096
#define CAP   4096
#define EPS   1e-5f
#define QKVW  6144

// ---------------- scratch ----------------
__device__ __half g_xn1h[(size_t)T_TOK * HIDD];
__device__ __half g_xn1l[(size_t)T_TOK * HIDD];
__device__ __half g_qkvh[(size_t)T_TOK * QKVW];
__device__ __half g_qkvl[(size_t)T_TOK * QKVW];
__device__ __half g_atth[(size_t)T_TOK * HIDD];
__device__ __half g_attl[(size_t)T_TOK * HIDD];
__device__ float  g_x2  [(size_t)T_TOK * HIDD];
__device__ __half g_xn2h[(size_t)T_TOK * HIDD];
__device__ __half g_acth[(size_t)NE * CAP * INTER];
__device__ float  g_yb  [(size_t)NE * CAP * HIDD];
__device__ __half g_wqkvh[(size_t)QKVW * HIDD];
__device__ __half g_wqkvl[(size_t)QKVW * HIDD];
__device__ __half g_woh[(size_t)HIDD * HIDD];
__device__ __half g_wol[(size_t)HIDD * HIDD];
__device__ __half g_wguh[(size_t)NE * 2 * INTER * HIDD];  // interleaved gate/up rows
__device__ __half g_wdh[(size_t)NE * HIDD * INTER];
__device__ int    g_cnt[NE];
__device__ int    g_gather[NE * CAP];
__device__ int2   g_slots[T_TOK];
__device__ float2 g_wts[T_TOK];

// ---------------- helpers ----------------
__device__ __forceinline__ void mma16(float* c, const uint32_t* a, uint32_t b0, uint32_t b1) {
    asm volatile(
        "mma.sync.aligned.m16n8k16.row.col.f32.f16.f16.f32 "
        "{%0,%1,%2,%3}, {%4,%5,%6,%7}, {%8,%9}, {%0,%1,%2,%3};"
        : "+f"(c[0]), "+f"(c[1]), "+f"(c[2]), "+f"(c[3])
        : "r"(a[0]), "r"(a[1]), "r"(a[2]), "r"(a[3]), "r"(b0), "r"(b1));
}
__device__ __forceinline__ void ldm_x4(uint32_t* r, uint32_t saddr) {
    asm volatile("ldmatrix.sync.aligned.m8n8.x4.shared.b16 {%0,%1,%2,%3}, [%4];"
                 : "=r"(r[0]), "=r"(r[1]), "=r"(r[2]), "=r"(r[3]) : "r"(saddr));
}
__device__ __forceinline__ void cp_async16s(uint32_t saddr, const void* gmem) {
    asm volatile("cp.async.cg.shared.global [%0], [%1], 16;\n" :: "r"(saddr), "l"(gmem));
}
__device__ __forceinline__ void cp_commit() { asm volatile("cp.async.commit_group;\n"); }
template <int N>
__device__ __forceinline__ void cp_wait() { asm volatile("cp.async.wait_group %0;\n" :: "n"(N)); }
__device__ __forceinline__ uint32_t ld32s(const __half* p) { return *(const uint32_t*)p; }
__device__ __forceinline__ void split16(float x, __half& h, __half& l) {
    h = __float2half_rn(x);
    l = __float2half_rn(x - __half2float(h));
}
// swizzled byte offset within an 8192B tile: row in [0,128), halfoff multiple of 8 in [0,32)
__device__ __forceinline__ uint32_t swz8(int row, int halfoff) {
    return (uint32_t)(row * 64 + ((((halfoff >> 3) ^ ((row >> 1) & 3)) << 4)));
}

// =========================================================================
// unified fp16 GEMM: C[M,N] = A[M,K] @ B[N,K]^T
//   NSTAGE-deep cp.async ring; XOR-swizzled smem tiles (64B rows, no pad)
// =========================================================================
#define HBM 128
#define HBN 128
#define HBK 32
#define TILE_B 8192

template <int NSTAGE, bool SPLIT, bool MOE, bool GATHER, bool EPI16, bool SWIGLU>
__global__ __launch_bounds__(256)
void hgemm(const __half* __restrict__ Ah, const __half* __restrict__ Al,
           const __half* __restrict__ Bh, const __half* __restrict__ Bl,
           const float* __restrict__ resid, float* __restrict__ Cf,
           __half* __restrict__ Ch, __half* __restrict__ Cl,
           int M, int N, int K, size_t aes, size_t bes, size_t ces) {
    extern __shared__ __half hsm[];
    __shared__ int rows_s[HBM];
    const int t = threadIdx.x, lane = t & 31, wid = t >> 5;
    const int lq = lane >> 2, lr = lane & 3;
    const int lrow16 = lane & 15, lsel = lane >> 4;
    const int rb = (wid >> 2) * 64, cb = (wid & 3) * 32;
    const int bm = blockIdx.y * HBM, bn = blockIdx.x * HBN;

    if (MOE) {
        int e = blockIdx.z;
        M = g_cnt[e];
        if (bm >= M) return;
        Ah += (size_t)e * aes;
        Bh += (size_t)e * bes;
        if (SWIGLU) Ch += (size_t)e * ces; else Cf += (size_t)e * ces;
        if (GATHER && t < HBM) {
            int r = bm + t;
            if (r >= M) r = M - 1;
            rows_s[t] = g_gather[e * CAP + r];
        }
        if (GATHER) __syncthreads();
    }

    const uint32_t sbase = (uint32_t)__cvta_generic_to_shared(hsm);
    const int IA_H = 0, IA_L = 1, IB_H = SPLIT ? 2 : 1, IB_L = 3;
    auto tb = [&](int arr, int buf) { return sbase + (uint32_t)(arr * NSTAGE + buf) * TILE_B; };

    float acc[4][4][4];
#pragma unroll
    for (int i = 0; i < 4; i++)
#pragma unroll
        for (int j = 0; j < 4; j++)
#pragma unroll
            for (int f = 0; f < 4; f++) acc[i][j][f] = 0.f;

    // per-thread load slots: 512 slots (128 rows x 4 segs of 8 halves), 2/thread
    uint32_t soff[2];
    size_t aoff[2], boff[2];
#pragma unroll
    for (int i = 0; i < 2; i++) {
        int slot = t + 256 * i;
        int row = slot >> 2, sg = (slot & 3) * 8;
        soff[i] = swz8(row, sg);
        size_t ar = GATHER ? (size_t)rows_s[row] : (size_t)(bm + row);
        aoff[i] = ar * K + sg;
        boff[i] = (size_t)(bn + row) * K + sg;
    }

    auto issue = [&](int c, int buf) {
        const int k0 = c * HBK;
#pragma unroll
        for (int i = 0; i < 2; i++) {
            cp_async16s(tb(IA_H, buf) + soff[i], Ah + aoff[i] + k0);
            cp_async16s(tb(IB_H, buf) + soff[i], Bh + boff[i] + k0);
            if (SPLIT) {
                cp_async16s(tb(IA_L, buf) + soff[i], Al + aoff[i] + k0);
                cp_async16s(tb(IB_L, buf) + soff[i], Bl + boff[i] + k0);
            }
        }
    };

    auto compute = [&](int buf) {
        const uint32_t tAh = tb(IA_H, buf), tBh = tb(IB_H, buf);
        const uint32_t tAl = tb(IA_L, buf), tBl = tb(IB_L, buf);
#pragma unroll
        for (int ks = 0; ks < 2; ks++) {
            const int hoff = ks * 16 + lsel * 8;
            uint32_t ah[4][4], al[4][4], bh[4][2], bl[4][2];
#pragma unroll
            for (int mt = 0; mt < 4; mt++) {
                uint32_t off = swz8(rb + mt * 16 + lrow16, hoff);
                ldm_x4(ah[mt], tAh + off);
                if (SPLIT) ldm_x4(al[mt], tAl + off);
            }
#pragma unroll
            for (int np = 0; np < 2; np++) {
                uint32_t off = swz8(cb + np * 16 + lrow16, hoff);
                uint32_t r[4];
                ldm_x4(r, tBh + off);
                bh[2 * np][0] = r[0]; bh[2 * np][1] = r[2];
                bh[2 * np + 1][0] = r[1]; bh[2 * np + 1][1] = r[3];
                if (SPLIT) {
                    ldm_x4(r, tBl + off);
                    bl[2 * np][0] = r[0]; bl[2 * np][1] = r[2];
                    bl[2 * np + 1][0] = r[1]; bl[2 * np + 1][1] = r[3];
                }
            }
#pragma unroll
            for (int mt = 0; mt < 4; mt++)
#pragma unroll
                for (int nt = 0; nt < 4; nt++) {
                    mma16(acc[mt][nt], ah[mt], bh[nt][0], bh[nt][1]);
                    if (SPLIT) {
                        mma16(acc[mt][nt], ah[mt], bl[nt][0], bl[nt][1]);
                        mma16(acc[mt][nt], al[mt], bh[nt][0], bh[nt][1]);
                    }
                }
        }
    };

    const int nk = K / HBK;
    // prologue: fill NSTAGE-1 stages, one group each
#pragma unroll
    for (int s = 0; s < NSTAGE - 1; s++) {
        if (s < nk) issue(s, s);
        cp_commit();
    }
    for (int c = 0; c < nk; c++) {
        __syncthreads();                 // prev compute done before refilling its buffer
        const int n = c + NSTAGE - 1;
        if (n < nk) issue(n, n % NSTAGE);
        cp_commit();                     // uniform group count
        cp_wait<NSTAGE - 1>();           // chunk c resident (in-order groups)
        __syncthreads();
        compute(c % NSTAGE);
    }

#pragma unroll
    for (int mt = 0; mt < 4; mt++)
#pragma unroll
        for (int nt = 0; nt < 4; nt++) {
            int r0g = bm + rb + mt * 16 + lq;
            int r1g = r0g + 8;
            int c0 = bn + cb + nt * 8 + lr * 2;
            if (SWIGLU) {
                int oc = c0 >> 1;
                if (r0g < M) {
                    float g = acc[mt][nt][0], u = acc[mt][nt][1];
                    Ch[(size_t)r0g * INTER + oc] =
                        __float2half_rn(g / (1.f + __expf(-g)) * u);
                }
                if (r1g < M) {
                    float g = acc[mt][nt][2], u = acc[mt][nt][3];
                    Ch[(size_t)r1g * INTER + oc] =
                        __float2half_rn(g / (1.f + __expf(-g)) * u);
                }
            } else if (EPI16) {
                __half h0, l0, h1, l1;
                split16(acc[mt][nt][0], h0, l0); split16(acc[mt][nt][1], h1, l1);
                *(__half2*)(Ch + (size_t)r0g * N + c0) = __halves2half2(h0, h1);
                *(__half2*)(Cl + (size_t)r0g * N + c0) = __halves2half2(l0, l1);
                split16(acc[mt][nt][2], h0, l0); split16(acc[mt][nt][3], h1, l1);
                *(__half2*)(Ch + (size_t)r1g * N + c0) = __halves2half2(h0, h1);
                *(__half2*)(Cl + (size_t)r1g * N + c0) = __halves2half2(l0, l1);
            } else {
                if (!MOE || r0g < M) {
                    float2 v0 = make_float2(acc[mt][nt][0], acc[mt][nt][1]);
                    if (resid) {
                        v0.x += resid[(size_t)r0g * N + c0];
                        v0.y += resid[(size_t)r0g * N + c0 + 1];
                    }
                    *(float2*)(Cf + (size_t)r0g * N + c0) = v0;
                }
                if (!MOE || r1g < M) {
                    float2 v1 = make_float2(acc[mt][nt][2], acc[mt][nt][3]);
                    if (resid) {
                        v1.x += resid[(size_t)r1g * N + c0];
                        v1.y += resid[(size_t)r1g * N + c0 + 1];
                    }
                    *(float2*)(Cf + (size_t)r1g * N + c0) = v1;
                }
            }
        }
}

// =========================================================================
// flash attention: fp16-split mma, causal, 64q x 64k tiles, 4 warps
// =========================================================================
#define QS 136
#define VS 72
#define FLASH_SMEM ((4 * 64 * QS + 2 * 128 * VS) * 2)

__global__ __launch_bounds__(128)
void flash_mma_k() {
    extern __shared__ __half fsm[];
    __half* Qh  = fsm;
    __half* Ql  = Qh + 64 * QS;
    __half* Kh  = Ql + 64 * QS;
    __half* Kl  = Kh + 64 * QS;
    __half* Vth = Kl + 64 * QS;
    __half* Vtl = Vth + 128 * VS;

    const int qt = blockIdx.x, head = blockIdx.y, b = blockIdx.z;
    const int t = threadIdx.x, wid = t >> 5, lane = t & 31;
    const int lq = lane >> 2, lr = lane & 3;
    const int wr = wid * 16;
    const float scale = 0.08838834764831845f;
    const size_t base = (size_t)b * SEQ * QKVW;
    const size_t qoff = (size_t)head * HD;
    const size_t koff = 2048 + qoff, voff = 4096 + qoff;

    for (int i = t; i < 64 * 16; i += 128) {
        int r = i >> 4, sg = (i & 15) * 8;
        size_t g = base + (size_t)(qt * 64 + r) * QKVW + qoff + sg;
        *(uint4*)(Qh + r * QS + sg) = *(const uint4*)(g_qkvh + g);
        *(uint4*)(Ql + r * QS + sg) = *(const uint4*)(g_qkvl + g);
    }

    float out[16][4];
#pragma unroll
    for (int i = 0; i < 16; i++)
#pragma unroll
        for (int j = 0; j < 4; j++) out[i][j] = 0.f;
    float m0 = -INFINITY, m1 = -INFINITY, l0 = 0.f, l1 = 0.f;

    for (int kt = 0; kt <= qt; kt++) {
        __syncthreads();
        for (int i = t; i < 64 * 16; i += 128) {
            int r = i >> 4, sg = (i & 15) * 8;
            size_t g = base + (size_t)(kt * 64 + r) * QKVW + koff + sg;
            *(uint4*)(Kh + r * QS + sg) = *(const uint4*)(g_qkvh + g);
            *(uint4*)(Kl + r * QS + sg) = *(const uint4*)(g_qkvl + g);
        }
        for (int i = t; i < 64 * 64; i += 128) {
            int r = i >> 6, dp = i & 63;
            size_t g = base + (size_t)(kt * 64 + r) * QKVW + voff + dp * 2;
            __half2 vh = *(const __half2*)(g_qkvh + g);
            __half2 vl = *(const __half2*)(g_qkvl + g);
            Vth[(2 * dp) * VS + r]     = __low2half(vh);
            Vth[(2 * dp + 1) * VS + r] = __high2half(vh);
            Vtl[(2 * dp) * VS + r]     = __low2half(vl);
            Vtl[(2 * dp + 1) * VS + r] = __high2half(vl);
        }
        __syncthreads();

        float s[8][4];
#pragma unroll
        for (int i = 0; i < 8; i++)
#pragma unroll
            for (int j = 0; j < 4; j++) s[i][j] = 0.f;

        for (int kc = 0; kc < 8; kc++) {
            uint32_t ah[4], al[4];
            const __half* qp = Qh + (wr + lq) * QS + kc * 16 + lr * 2;
            const __half* ql = Ql + (wr + lq) * QS + kc * 16 + lr * 2;
            ah[0] = ld32s(qp);     ah[1] = ld32s(qp + 8 * QS);
            ah[2] = ld32s(qp + 8); ah[3] = ld32s(qp + 8 * QS + 8);
            al[0] = ld32s(ql);     al[1] = ld32s(ql + 8 * QS);
            al[2] = ld32s(ql + 8); al[3] = ld32s(ql + 8 * QS + 8);
#pragma unroll
            for (int nt = 0; nt < 8; nt++) {
                const __half* kp = Kh + (nt * 8 + lq) * QS + kc * 16 + lr * 2;
                const __half* kl = Kl + (nt * 8 + lq) * QS + kc * 16 + lr * 2;
                uint32_t bh0 = ld32s(kp), bh1 = ld32s(kp + 8);
                uint32_t bl0 = ld32s(kl), bl1 = ld32s(kl + 8);
                mma16(s[nt], ah, bh0, bh1);
                mma16(s[nt], ah, bl0, bl1);
                mma16(s[nt], al, bh0, bh1);
            }
        }

        const bool diag = (kt == qt);
#pragma unroll
        for (int nt = 0; nt < 8; nt++)
#pragma unroll
            for (int cc = 0; cc < 4; cc++) {
                float v = s[nt][cc] * scale;
                if (diag) {
                    int col = nt * 8 + lr * 2 + (cc & 1);
                    int row = wr + lq + ((cc >= 2) ? 8 : 0);
                    if (col > row) v = -INFINITY;
                }
                s[nt][cc] = v;
            }

        float mx0 = m0, mx1 = m1;
#pragma unroll
        for (int nt = 0; nt < 8; nt++) {
            mx0 = fmaxf(mx0, fmaxf(s[nt][0], s[nt][1]));
            mx1 = fmaxf(mx1, fmaxf(s[nt][2], s[nt][3]));
        }
        mx0 = fmaxf(mx0, __shfl_xor_sync(0xffffffffu, mx0, 1));
        mx0 = fmaxf(mx0, __shfl_xor_sync(0xffffffffu, mx0, 2));
        mx1 = fmaxf(mx1, __shfl_xor_sync(0xffffffffu, mx1, 1));
        mx1 = fmaxf(mx1, __shfl_xor_sync(0xffffffffu, mx1, 2));
        float a0 = __expf(m0 - mx0), a1 = __expf(m1 - mx1);
        m0 = mx0; m1 = mx1;
        float sum0 = 0.f, sum1 = 0.f;
#pragma unroll
        for (int nt = 0; nt < 8; nt++) {
            s[nt][0] = __expf(s[nt][0] - mx0);
            s[nt][1] = __expf(s[nt][1] - mx0);
            s[nt][2] = __expf(s[nt][2] - mx1);
            s[nt][3] = __expf(s[nt][3] - mx1);
            sum0 += s[nt][0] + s[nt][1];
            sum1 += s[nt][2] + s[nt][3];
        }
        sum0 += __shfl_xor_sync(0xffffffffu, sum0, 1);
        sum0 += __shfl_xor_sync(0xffffffffu, sum0, 2);
        sum1 += __shfl_xor_sync(0xffffffffu, sum1, 1);
        sum1 += __shfl_xor_sync(0xffffffffu, sum1, 2);
        l0 = l0 * a0 + sum0;
        l1 = l1 * a1 + sum1;

#pragma unroll
        for (int nt = 0; nt < 16; nt++) {
            out[nt][0] *= a0; out[nt][1] *= a0;
            out[nt][2] *= a1; out[nt][3] *= a1;
        }

#pragma unroll
        for (int kc = 0; kc < 4; kc++) {
            const int t0 = 2 * kc, t1 = 2 * kc + 1;
            uint32_t ph[4], pl[4];
            {
                __half2 h, l;
                h = __floats2half2_rn(s[t0][0], s[t0][1]);
                l = __floats2half2_rn(s[t0][0] - __low2float(h), s[t0][1] - __high2float(h));
                ph[0] = *(uint32_t*)&h; pl[0] = *(uint32_t*)&l;
                h = __floats2half2_rn(s[t0][2], s[t0][3]);
                l = __floats2half2_rn(s[t0][2] - __low2float(h), s[t0][3] - __high2float(h));
                ph[1] = *(uint32_t*)&h; pl[1] = *(uint32_t*)&l;
                h = __floats2half2_rn(s[t1][0], s[t1][1]);
                l = __floats2half2_rn(s[t1][0] - __low2float(h), s[t1][1] - __high2float(h));
                ph[2] = *(uint32_t*)&h; pl[2] = *(uint32_t*)&l;
                h = __floats2half2_rn(s[t1][2], s[t1][3]);
                l = __floats2half2_rn(s[t1][2] - __low2float(h), s[t1][3] - __high2float(h));
                ph[3] = *(uint32_t*)&h; pl[3] = *(uint32_t*)&l;
            }
#pragma unroll
            for (int nt = 0; nt < 16; nt++) {
                const __half* vp = Vth + (nt * 8 + lq) * VS + kc * 16 + lr * 2;
                const __half* vl = Vtl + (nt * 8 + lq) * VS + kc * 16 + lr * 2;
                uint32_t bh0 = ld32s(vp), bh1 = ld32s(vp + 8);
                uint32_t bl0 = ld32s(vl), bl1 = ld32s(vl + 8);
                mma16(out[nt], ph, bh0, bh1);
                mma16(out[nt], ph, bl0, bl1);
                mma16(out[nt], pl, bh0, bh1);
            }
        }
    }

    const float inv0 = 1.f / l0, inv1 = 1.f / l1;
    const int row0 = qt * 64 + wr + lq;
    const size_t o0 = ((size_t)b * SEQ + row0) * HIDD + head * HD;
    const size_t o1 = o0 + 8 * HIDD;
#pragma unroll
    for (int nt = 0; nt < 16; nt++) {
        int c = nt * 8 + lr * 2;
        __half h0, lo0, h1, lo1;
        split16(out[nt][0] * inv0, h0, lo0);
        split16(out[nt][1] * inv0, h1, lo1);
        *(__half2*)(g_atth + o0 + c) = __halves2half2(h0, h1);
        *(__half2*)(g_attl + o0 + c) = __halves2half2(lo0, lo1);
        split16(out[nt][2] * inv1, h0, lo0);
        split16(out[nt][3] * inv1, h1, lo1);
        *(__half2*)(g_atth + o1 + c) = __halves2half2(h0, h1);
        *(__half2*)(g_attl + o1 + c) = __halves2half2(lo0, lo1);
    }
}

// ---------------- RMSNorm (ln1: fp16 h/l out) ----------------
__global__ void rmsnorm_k(const float* __restrict__ x, const float* __restrict__ w,
                          __half* __restrict__ yh, __half* __restrict__ yl) {
    int tok = blockIdx.x;
    const float* xr = x + (size_t)tok * HIDD;
    float s = 0.f;
    for (int i = threadIdx.x * 4; i < HIDD; i += blockDim.x * 4) {
        float4 v = *(const float4*)(xr + i);
        s += v.x * v.x + v.y * v.y + v.z * v.z + v.w * v.w;
    }
    __shared__ float red[32];
    for (int o = 16; o > 0; o >>= 1) s += __shfl_xor_sync(0xffffffffu, s, o);
    if ((threadIdx.x & 31) == 0) red[threadIdx.x >> 5] = s;
    __syncthreads();
    if (threadIdx.x < 32) {
        float v = (threadIdx.x < (blockDim.x >> 5)) ? red[threadIdx.x] : 0.f;
        for (int o = 4; o > 0; o >>= 1) v += __shfl_xor_sync(0xffffffffu, v, o);
        if (threadIdx.x == 0) red[0] = rsqrtf(v / (float)HIDD + EPS);
    }
    __syncthreads();
    float sc = red[0];
    for (int i = threadIdx.x * 4; i < HIDD; i += blockDim.x * 4) {
        float4 v = *(const float4*)(xr + i);
        float4 wv = *(const float4*)(w + i);
        float4 o;
        o.x = v.x * sc * wv.x; o.y = v.y * sc * wv.y;
        o.z = v.z * sc * wv.z; o.w = v.w * sc * wv.w;
        size_t idx = (size_t)tok * HIDD + i;
        __half h0, l0h, h1, l1h, h2, l2h, h3, l3h;
        split16(o.x, h0, l0h); split16(o.y, h1, l1h);
        split16(o.z, h2, l2h); split16(o.w, h3, l3h);
        *(__half2*)(yh + idx) = __halves2half2(h0, h1);
        *(__half2*)(yh + idx + 2) = __halves2half2(h2, h3);
        *(__half2*)(yl + idx) = __halves2half2(l0h, l1h);
        *(__half2*)(yl + idx + 2) = __halves2half2(l2h, l3h);
    }
}

// ---------------- fused ln2 + router (fp16 xn2 out + top-2 routing) ----------------
__global__ void rmsnorm_router_k(const float* __restrict__ x2, const float* __restrict__ w,
                                 const float* __restrict__ Wr, __half* __restrict__ yh) {
    const int tok = blockIdx.x;
    __shared__ float xs[HIDD];          // x2 * w (pre-scale)
    __shared__ float red[32];
    __shared__ float lg[NE];
    const float* xr = x2 + (size_t)tok * HIDD;
    float s = 0.f;
    for (int i = threadIdx.x * 4; i < HIDD; i += 1024) {
        float4 v = *(const float4*)(xr + i);
        float4 wv = *(const float4*)(w + i);
        s += v.x * v.x + v.y * v.y + v.z * v.z + v.w * v.w;
        xs[i] = v.x * wv.x; xs[i + 1] = v.y * wv.y;
        xs[i + 2] = v.z * wv.z; xs[i + 3] = v.w * wv.w;
    }
    for (int o = 16; o > 0; o >>= 1) s += __shfl_xor_sync(0xffffffffu, s, o);
    if ((threadIdx.x & 31) == 0) red[threadIdx.x >> 5] = s;
    __syncthreads();
    if (threadIdx.x < 32) {
        float v = (threadIdx.x < 8) ? red[threadIdx.x] : 0.f;
        for (int o = 4; o > 0; o >>= 1) v += __shfl_xor_sync(0xffffffffu, v, o);
        if (threadIdx.x == 0) red[0] = rsqrtf(v / (float)HIDD + EPS);
    }
    __syncthreads();
    const float sc = red[0];
    for (int i = threadIdx.x * 4; i < HIDD; i += 1024) {
        size_t idx = (size_t)tok * HIDD + i;
        *(__half2*)(yh + idx) = __floats2half2_rn(xs[i] * sc, xs[i + 1] * sc);
        *(__half2*)(yh + idx + 2) = __floats2half2_rn(xs[i + 2] * sc, xs[i + 3] * sc);
    }
    const int wwid = threadIdx.x >> 5, lane = threadIdx.x & 31;
    const float* wr = Wr + (size_t)wwid * HIDD;
    float acc = 0.f;
    for (int i = lane * 4; i < HIDD; i += 128) {
        float4 bb = *(const float4*)(wr + i);
        acc += xs[i] * sc * bb.x + xs[i + 1] * sc * bb.y +
               xs[i + 2] * sc * bb.z + xs[i + 3] * sc * bb.w;
    }
    for (int o = 16; o > 0; o >>= 1) acc += __shfl_xor_sync(0xffffffffu, acc, o);
    if (lane == 0) lg[wwid] = acc;
    __syncthreads();
    if (threadIdx.x == 0) {
        float b1 = -INFINITY; int i1 = 0;
        for (int e = 0; e < NE; e++) if (lg[e] > b1) { b1 = lg[e]; i1 = e; }
        float b2 = -INFINITY; int i2 = (i1 == 0) ? 1 : 0;
        for (int e = 0; e < NE; e++) if (e != i1 && lg[e] > b2) { b2 = lg[e]; i2 = e; }
        float eo = expf(b2 - b1);
        float w1 = 1.f / (1.f + eo);
        float w2 = eo / (1.f + eo);
        int p1 = atomicAdd(&g_cnt[i1], 1);
        int p2 = atomicAdd(&g_cnt[i2], 1);
        g_gather[i1 * CAP + p1] = tok;
        g_gather[i2 * CAP + p2] = tok;
        g_slots[tok] = make_int2(i1 * CAP + p1, i2 * CAP + p2);
        g_wts[tok] = make_float2(w1, w2);
    }
}

// ---------------- weight cvt (wide, streaming) ----------------
__device__ __forceinline__ uint32_t packsplit_h(float a, float b) {
    __half2 t = __floats2half2_rn(a, b);
    return *(uint32_t*)&t;
}

__global__ void cvt16_k(const float* __restrict__ s, __half* __restrict__ h,
                        __half* __restrict__ l, size_t n) {
    size_t i = ((size_t)blockIdx.x * blockDim.x + threadIdx.x) * 8;
    if (i >= n) return;
    float4 v0 = __ldcs((const float4*)(s + i));
    float4 v1 = __ldcs((const float4*)(s + i + 4));
    float f[8] = {v0.x, v0.y, v0.z, v0.w, v1.x, v1.y, v1.z, v1.w};
    uint32_t hw[4], lw[4];
#pragma unroll
    for (int j = 0; j < 4; j++) {
        __half ha, la, hb, lb;
        split16(f[2 * j], ha, la); split16(f[2 * j + 1], hb, lb);
        __half2 hh = __halves2half2(ha, hb), ll = __halves2half2(la, lb);
        hw[j] = *(uint32_t*)&hh; lw[j] = *(uint32_t*)&ll;
    }
    __stcs((uint4*)(h + i), make_uint4(hw[0], hw[1], hw[2], hw[3]));
    __stcs((uint4*)(l + i), make_uint4(lw[0], lw[1], lw[2], lw[3]));
}

__global__ void cvt16h_k(const float* __restrict__ s, __half* __restrict__ h, size_t n) {
    size_t i = ((size_t)blockIdx.x * blockDim.x + threadIdx.x) * 8;
    if (i >= n) return;
    float4 v0 = __ldcs((const float4*)(s + i));
    float4 v1 = __ldcs((const float4*)(s + i + 4));
    __stcs((uint4*)(h + i),
           make_uint4(packsplit_h(v0.x, v0.y), packsplit_h(v0.z, v0.w),
                      packsplit_h(v1.x, v1.y), packsplit_h(v1.z, v1.w)));
}

__global__ void cvt16h_il_k(const float* __restrict__ s, __half* __restrict__ h,
                            size_t n, int off) {
    size_t i = ((size_t)blockIdx.x * blockDim.x + threadIdx.x) * 8;
    if (i >= n) return;
    size_t row = i / HIDD;
    size_t e = row / INTER, j = row % INTER;
    size_t dst = (e * 2 * INTER + 2 * j + (size_t)off) * HIDD + (i % HIDD);
    float4 v0 = __ldcs((const float4*)(s + i));
    float4 v1 = __ldcs((const float4*)(s + i + 4));
    __stcs((uint4*)(h + dst),
           make_uint4(packsplit_h(v0.x, v0.y), packsplit_h(v0.z, v0.w),
                      packsplit_h(v1.x, v1.y), packsplit_h(v1.z, v1.w)));
}

// ---------------- router count reset ----------------
__global__ void zero_cnt_k() { if (threadIdx.x < NE) g_cnt[threadIdx.x] = 0; }

// ---------------- final combine ----------------
__global__ void combine_k(const float* __restrict__ x2, float* __restrict__ out) {
    const int tok = blockIdx.x;
    const int2 sl = g_slots[tok];
    const float2 w = g_wts[tok];
    const float* y1 = g_yb + (size_t)sl.x * HIDD;
    const float* y2 = g_yb + (size_t)sl.y * HIDD;
    for (int i = threadIdx.x * 4; i < HIDD; i += blockDim.x * 4) {
        float4 a = *(const float4*)(x2 + (size_t)tok * HIDD + i);
        float4 b = *(const float4*)(y1 + i);
        float4 c = *(const float4*)(y2 + i);
        float4 o;
        o.x = a.x + w.x * b.x + w.y * c.x;
        o.y = a.y + w.x * b.y + w.y * c.y;
        o.z = a.z + w.x * b.z + w.y * c.z;
        o.w = a.w + w.x * b.w + w.y * c.w;
        *(float4*)(out + (size_t)tok * HIDD + i) = o;
    }
}

// ---------------- launch ----------------
extern "C" void kernel_launch(void* const* d_in, const int* in_sizes, int n_in,
                              void* d_out, int out_size) {
    (void)in_sizes; (void)n_in; (void)out_size;
    const float* x    = (const float*)d_in[0];
    const float* Wq   = (const float*)d_in[1];
    const float* Wk   = (const float*)d_in[2];
    const float* Wv   = (const float*)d_in[3];
    const float* Wo   = (const float*)d_in[4];
    const float* wln1 = (const float*)d_in[5];
    const float* wln2 = (const float*)d_in[6];
    const float* Wr   = (const float*)d_in[7];
    const float* Wg   = (const float*)d_in[8];
    const float* Wu   = (const float*)d_in[9];
    const float* Wd   = (const float*)d_in[10];
    float* out = (float*)d_out;

    void* p;
#define SYM(var, sym) cudaGetSymbolAddress(&p, sym); var = (decltype(var))p
    __half *xn1h, *xn1l, *qkvh, *qkvl, *atth, *attl, *wqkvh, *wqkvl, *woh, *wol;
    __half *xn2h, *wguh, *wdh, *acth;
    float *x2, *yb;
    SYM(xn1h, g_xn1h); SYM(xn1l, g_xn1l);
    SYM(qkvh, g_qkvh); SYM(qkvl, g_qkvl);
    SYM(atth, g_atth); SYM(attl, g_attl);
    SYM(wqkvh, g_wqkvh); SYM(wqkvl, g_wqkvl);
    SYM(woh, g_woh); SYM(wol, g_wol);
    SYM(xn2h, g_xn2h); SYM(wguh, g_wguh); SYM(wdh, g_wdh);
    SYM(acth, g_acth);
    SYM(x2, g_x2); SYM(yb, g_yb);
#undef SYM

    static cudaStream_t s2 = nullptr;
    static cudaEvent_t ev_fork = nullptr, ev_wo = nullptr, ev_moe = nullptr;
    if (s2 == nullptr) {
        cudaStreamCreateWithFlags(&s2, cudaStreamNonBlocking);
        cudaEventCreateWithFlags(&ev_fork, cudaEventDisableTiming);
        cudaEventCreateWithFlags(&ev_wo, cudaEventDisableTiming);
        cudaEventCreateWithFlags(&ev_moe, cudaEventDisableTiming);
    }

    // split: 4 arrays x 3 stages x 8192B = 98304; single: 2 arrays x 3 stages x 8192B = 49152
    const int split_smem  = 4 * 3 * TILE_B;
    const int single_smem = 2 * 3 * TILE_B;
    cudaFuncSetAttribute((const void*)hgemm<3, true,  false, false, true,  false>,
                         cudaFuncAttributeMaxDynamicSharedMemorySize, split_smem);
    cudaFuncSetAttribute((const void*)hgemm<3, true,  false, false, false, false>,
                         cudaFuncAttributeMaxDynamicSharedMemorySize, split_smem);
    cudaFuncSetAttribute((const void*)hgemm<3, false, true,  true,  false, true>,
                         cudaFuncAttributeMaxDynamicSharedMemorySize, single_smem);
    cudaFuncSetAttribute((const void*)hgemm<3, false, true,  false, false, false>,
                         cudaFuncAttributeMaxDynamicSharedMemorySize, single_smem);
    cudaFuncSetAttribute(flash_mma_k, cudaFuncAttributeMaxDynamicSharedMemorySize, FLASH_SMEM);

    const size_t HH = (size_t)HIDD * HIDD;
    const size_t EIH = (size_t)NE * INTER * HIDD;

    // ---- fork side stream: Wo + MoE weight conversions overlap QKV/flash ----
    cudaEventRecord(ev_fork, 0);
    cudaStreamWaitEvent(s2, ev_fork, 0);
    cvt16_k<<<(unsigned)(HH / 2048), 256, 0, s2>>>(Wo, woh, wol, HH);
    cudaEventRecord(ev_wo, s2);
    cvt16h_il_k<<<(unsigned)(EIH / 2048), 256, 0, s2>>>(Wg, wguh, EIH, 0);
    cvt16h_il_k<<<(unsigned)(EIH / 2048), 256, 0, s2>>>(Wu, wguh, EIH, 1);
    cvt16h_k<<<(unsigned)(EIH / 2048), 256, 0, s2>>>(Wd, wdh, EIH);
    cudaEventRecord(ev_moe, s2);

    // ---- main stream ----
    cvt16_k<<<(unsigned)(HH / 2048), 256>>>(Wq, wqkvh, wqkvl, HH);
    cvt16_k<<<(unsigned)(HH / 2048), 256>>>(Wk, wqkvh + HH, wqkvl + HH, HH);
    cvt16_k<<<(unsigned)(HH / 2048), 256>>>(Wv, wqkvh + 2 * HH, wqkvl + 2 * HH, HH);

    // 1) ln1 -> fp16 h/l
    rmsnorm_k<<<T_TOK, 256>>>(x, wln1, xn1h, xn1l);
    // 2) fused QKV projection (split, 3-stage swizzled ring, fp16 h/l epilogue)
    hgemm<3, true, false, false, true, false><<<dim3(QKVW / HBN, T_TOK / HBM), 256, split_smem>>>(
        xn1h, xn1l, wqkvh, wqkvl, nullptr, nullptr, qkvh, qkvl, T_TOK, QKVW, HIDD, 0, 0, 0);
    // 3) flash attention
    flash_mma_k<<<dim3(SEQ / 64, NH, NB), 128, FLASH_SMEM>>>();
    // 4) O projection + residual
    cudaStreamWaitEvent(0, ev_wo, 0);
    hgemm<3, true, false, false, false, false><<<dim3(HIDD / HBN, T_TOK / HBM), 256, split_smem>>>(
        atth, attl, woh, wol, x, x2, nullptr, nullptr, T_TOK, HIDD, HIDD, 0, 0, 0);
    // 5) fused ln2 + routing
    zero_cnt_k<<<1, 32>>>();
    rmsnorm_router_k<<<T_TOK, 256>>>(x2, wln2, Wr, xn2h);
    // 6) fused gate+up GEMM with SwiGLU epilogue
    cudaStreamWaitEvent(0, ev_moe, 0);
    hgemm<3, false, true, true, false, true><<<dim3(2 * INTER / HBN, CAP / HBM, NE), 256, single_smem>>>(
        xn2h, nullptr, wguh, nullptr, nullptr, nullptr, acth, nullptr,
        0, 2 * INTER, HIDD, 0, (size_t)2 * INTER * HIDD, (size_t)CAP * INTER);
    // 7) down GEMM
    hgemm<3, false, true, false, false, false><<<dim3(HIDD / HBN, CAP / HBM, NE), 256, single_smem>>>(
        acth, nullptr, wdh, nullptr, nullptr, yb, nullptr, nullptr,
        0, HIDD, INTER, (size_t)CAP * INTER, (size_t)HIDD * INTER, (size_t)CAP * HIDD);
    // 8) combine + final residual
    combine_k<<<T_TOK, 256>>>(x2, out);
}